// round 13
// baseline (speedup 1.0000x reference)
#include <cuda_runtime.h>
#include <math.h>
#include <stdint.h>

// ---------------- problem constants ----------------
#define BB 2
#define CC 180
#define CP 192              // padded channel stride (multiple of 32)
#define DD 16
#define HH 32
#define WW 32
#define LL 16384            // D*H*W
#define LT 32768            // B*L
#define NHEADS 6
#define HDIM 30
#define NTOK 512
#define NWIN 64
#define HIDD 720
#define HIDP 736            // padded fc2 K (multiple of 32)
#define QSCALE 0.18257418583505537f  // 30^-0.5

// ---------------- device scratch (zero-initialized; pads never written) ----------------
__device__ uint16_t g_xn[LT * CP];              // bf16, LN1 out
__device__ uint16_t g_ln2[LT * CP];             // bf16, LN2 out
__device__ uint16_t g_ao[LT * CP];              // bf16, attention out (window order)
__device__ float    g_x1[LT * CC];              // fp32 residual
__device__ uint16_t g_y1[LT * 64];              // bf16 conv1 out (gelu'd, 64-pad)
__device__ uint16_t g_y2[LT * CC];              // bf16 conv2 out + bias
__device__ uint16_t g_qkv[NWIN * 3 * NHEADS * NTOK * HDIM];  // bf16
__device__ uint16_t g_hbuf[LT * HIDP];          // bf16 fc1 gelu out (K-pad 736)
__device__ uint16_t g_biasT[NHEADS * NTOK * NTOK]; // bf16 [h][query][key]
__device__ uint16_t g_w1m[27 * 64 * 192];       // bf16 [tap][cout64][cin192]
__device__ uint16_t g_w2m[27 * 256 * 64];       // bf16 [tap][cout256-pad][cin64]
__device__ uint16_t g_wq[640 * 192];            // bf16 qkv_w (row-pad 640)
__device__ uint16_t g_wp[256 * 192];            // bf16 proj_w (row-pad 256)
__device__ uint16_t g_wf1[768 * 192];           // bf16 fc1_w (row-pad 768)
__device__ uint16_t g_wf2[256 * HIDP];          // bf16 fc2_w (row-pad 256)
__device__ float g_pool[2 * CC];
__device__ float g_catt[2 * CC];

// window (win, n) -> flat row b*LL + l  (bijection)
__device__ __forceinline__ int win_src_row(int r) {
    int win = r >> 9, n = r & 511;
    int sb = win >> 2, wq = win & 3;
    int b = sb >> 3, isp = sb & 7;
    int id = isp >> 2, ih = (isp >> 1) & 1, iw = isp & 1;
    int nhi = wq >> 1, nwi = wq & 1;
    int wd = n >> 6, wh = (n >> 3) & 7, ww = n & 7;
    int d = wd * 2 + id;
    int h = (nhi * 8 + wh) * 2 + ih;
    int w = (nwi * 8 + ww) * 2 + iw;
    return ((b * DD + d) * HH + h) * WW + w;
}

__device__ __forceinline__ float gelu_exact(float v) {
    return 0.5f * v * (1.f + erff(v * 0.70710678118654752f));
}

// pack two floats -> bf16x2 word (lo = first)
__device__ __forceinline__ uint32_t pk(float lo, float hi) {
    uint32_t r;
    asm("cvt.rn.bf16x2.f32 %0, %1, %2;" : "=r"(r) : "f"(hi), "f"(lo));
    return r;
}
__device__ __forceinline__ uint16_t f2b(float v) { return (uint16_t)pk(v, 0.f); }
__device__ __forceinline__ float b2f(uint32_t bits16) {
    return __int_as_float((int)(bits16 << 16));
}

__device__ __forceinline__ void mma16(float* c, const uint32_t* a, const uint32_t* b) {
    asm volatile(
        "mma.sync.aligned.m16n8k16.row.col.f32.bf16.bf16.f32 "
        "{%0,%1,%2,%3},{%4,%5,%6,%7},{%8,%9},{%0,%1,%2,%3};\n"
        : "+f"(c[0]), "+f"(c[1]), "+f"(c[2]), "+f"(c[3])
        : "r"(a[0]), "r"(a[1]), "r"(a[2]), "r"(a[3]), "r"(b[0]), "r"(b[1]));
}

// ldmatrix x4 (b16)
__device__ __forceinline__ void ldsm4(uint32_t* r, const void* p) {
    uint32_t addr = (uint32_t)__cvta_generic_to_shared(p);
    asm volatile("ldmatrix.sync.aligned.m8n8.x4.shared.b16 {%0,%1,%2,%3}, [%4];"
        : "=r"(r[0]), "=r"(r[1]), "=r"(r[2]), "=r"(r[3]) : "r"(addr));
}

// cp.async 16B, with zfill predication (sz=0 -> no memory access, zero fill)
__device__ __forceinline__ void cpa16(void* smem, const void* gmem, bool pred) {
    uint32_t s = (uint32_t)__cvta_generic_to_shared(smem);
    int sz = pred ? 16 : 0;
    asm volatile("cp.async.cg.shared.global [%0], [%1], 16, %2;\n"
                 :: "r"(s), "l"(gmem), "r"(sz));
}
__device__ __forceinline__ void cpcommit() {
    asm volatile("cp.async.commit_group;\n");
}
template <int N>
__device__ __forceinline__ void cpwait() {
    asm volatile("cp.async.wait_group %0;\n" :: "n"(N));
}

// warp tile 32x32 over BK=32 (conv1)
__device__ __forceinline__ void tile_mma32(const uint32_t (*As)[20], const uint32_t (*Bs)[20],
                                           float acc[2][4][4], int wm, int wn, int lane) {
    const int ar = wm * 32 + (lane & 15);
    const int aw = (lane >> 4) * 4;
    const int br = wn * 32 + ((lane >> 4) << 3) + (lane & 7);
    const int bw = ((lane >> 3) & 1) * 4;
#pragma unroll
    for (int ks = 0; ks < 2; ks++) {
        uint32_t a[2][4], b[2][4];
        ldsm4(a[0], &As[ar][ks * 8 + aw]);
        ldsm4(a[1], &As[ar + 16][ks * 8 + aw]);
        ldsm4(b[0], &Bs[br][ks * 8 + bw]);
        ldsm4(b[1], &Bs[br + 16][ks * 8 + bw]);
#pragma unroll
        for (int mt = 0; mt < 2; mt++)
#pragma unroll
            for (int p = 0; p < 2; p++) {
                mma16(acc[mt][p * 2],     a[mt], b[p]);
                mma16(acc[mt][p * 2 + 1], a[mt], b[p] + 2);
            }
    }
}

// warp tile 32x64 over BK=32 (BN=128 kernels)
__device__ __forceinline__ void tile_mma64(const uint32_t (*As)[20], const uint32_t (*Bs)[20],
                                           float acc[2][8][4], int wm, int wn, int lane) {
    const int ar = wm * 32 + (lane & 15);
    const int aw = (lane >> 4) * 4;
    const int br = ((lane >> 4) << 3) + (lane & 7);
    const int bw = ((lane >> 3) & 1) * 4;
#pragma unroll
    for (int ks = 0; ks < 2; ks++) {
        uint32_t a[2][4], b[4][4];
        ldsm4(a[0], &As[ar][ks * 8 + aw]);
        ldsm4(a[1], &As[ar + 16][ks * 8 + aw]);
#pragma unroll
        for (int p = 0; p < 4; p++)
            ldsm4(b[p], &Bs[wn * 64 + p * 16 + br][ks * 8 + bw]);
#pragma unroll
        for (int mt = 0; mt < 2; mt++)
#pragma unroll
            for (int p = 0; p < 4; p++) {
                mma16(acc[mt][p * 2],     a[mt], b[p]);
                mma16(acc[mt][p * 2 + 1], a[mt], b[p] + 2);
            }
    }
}

#define G2_SMEM (2 * 3 * 128 * 20 * 4)   // 61440 bytes

// ---------------- prep kernels ----------------
__global__ void wpack_kernel(const float* __restrict__ w, uint16_t* __restrict__ out,
                             int N, int K, int Ksm) {
    int idx = blockIdx.x * 256 + threadIdx.x;
    if (idx >= N * Ksm) return;
    int n = idx / Ksm, k = idx - n * Ksm;
    out[idx] = (k < K) ? f2b(w[n * K + k]) : (uint16_t)0;
}

__global__ void repack1_kernel(const float* __restrict__ cw1, uint16_t* __restrict__ w1m) {
    int idx = blockIdx.x * 256 + threadIdx.x;
    if (idx >= 27 * 64 * 192) return;
    int tap = idx / (64 * 192);
    int rem = idx - tap * 64 * 192;
    int o = rem / 192, c = rem - o * 192;
    w1m[idx] = (o < 60 && c < 180) ? f2b(cw1[(o * 180 + c) * 27 + tap]) : (uint16_t)0;
}

// w2m layout: [tap][cout 256-pad][cin 64]; write only o<192 band, pad stays zero
__global__ void repack2_kernel(const float* __restrict__ cw2, uint16_t* __restrict__ w2m) {
    int idx = blockIdx.x * 256 + threadIdx.x;
    if (idx >= 27 * 192 * 64) return;
    int tap = idx / (192 * 64);
    int rem = idx - tap * 192 * 64;
    int o = rem >> 6, c = rem & 63;
    w2m[((long)tap * 256 + o) * 64 + c] =
        (o < 180 && c < 60) ? f2b(cw2[(o * 60 + c) * 27 + tap]) : (uint16_t)0;
}

// bias table: [h][query][key] bf16
__global__ void biasprep_kernel(const int* __restrict__ rpi, const float* __restrict__ rpb,
                                uint16_t* __restrict__ biasT) {
    int q = blockIdx.x, k = threadIdx.x;
    int t = rpi[q * 512 + k];
#pragma unroll
    for (int h = 0; h < NHEADS; h++)
        biasT[(h * 512 + q) * 512 + k] = f2b(rpb[t * NHEADS + h]);
}

__global__ void zero_pool_kernel(float* __restrict__ pool) {
    if (threadIdx.x < 2 * CC) pool[threadIdx.x] = 0.f;
}

// ---------------- layernorm (warp per row), bf16 out ----------------
__global__ void __launch_bounds__(256) ln_kernel(const float* __restrict__ in, int ins,
        const float* __restrict__ gg, const float* __restrict__ bb,
        uint16_t* __restrict__ outp, int outs) {
    int row = blockIdx.x * 8 + (threadIdx.x >> 5);
    int lane = threadIdx.x & 31;
    const float* p = in + (long)row * ins;
    float v[6];
    float s = 0.f;
#pragma unroll
    for (int i = 0; i < 6; i++) {
        int c = lane + i * 32;
        v[i] = (c < CC) ? p[c] : 0.f;
        s += v[i];
    }
    for (int o = 16; o; o >>= 1) s += __shfl_xor_sync(~0u, s, o);
    float mean = s * (1.f / CC);
    float vs = 0.f;
#pragma unroll
    for (int i = 0; i < 6; i++) {
        int c = lane + i * 32;
        float d = (c < CC) ? (v[i] - mean) : 0.f;
        vs += d * d;
    }
    for (int o = 16; o; o >>= 1) vs += __shfl_xor_sync(~0u, vs, o);
    float inv = rsqrtf(vs * (1.f / CC) + 1e-5f);
    uint16_t* q = outp + (long)row * outs;
#pragma unroll
    for (int i = 0; i < 6; i++) {
        int c = lane + i * 32;
        if (c < CC) q[c] = f2b((v[i] - mean) * inv * gg[c] + bb[c]);
    }
}

// ---------------- bf16 MMA GEMM, BM=128 BN=128, cp.async 3-stage, BK=32 ----------------
// EPI 0: qkv scatter bf16 (+q scale); 1: proj scatter + triple residual (e1 = bf16 y2);
//     2: gelu -> bf16 (stride OS); 3: residual -> fp32 out
template <int EPI, bool GATHER>
__global__ void __launch_bounds__(256, 2) mma_gemm(
        const uint16_t* __restrict__ A, int Asr,
        const uint16_t* __restrict__ Wm, const float* __restrict__ bias,
        void* __restrict__ CoutV, int Nc, int Ksm, int OS,
        const float* __restrict__ e0, const uint16_t* __restrict__ e1,
        const float* __restrict__ e2) {
    extern __shared__ uint32_t sm[];
    uint32_t (*As)[128][20] = (uint32_t (*)[128][20])sm;
    uint32_t (*Bs)[128][20] = (uint32_t (*)[128][20])(sm + 3 * 128 * 20);
    const int tid = threadIdx.x;
    const int row0 = blockIdx.x * 128, col0 = blockIdx.y * 128;
    const int T = Ksm >> 5;

    int ar[2], akq[2];
    long abase[2], bbase[2];
#pragma unroll
    for (int i = 0; i < 2; i++) {
        int id = tid + i * 256;
        ar[i] = id >> 2;
        akq[i] = id & 3;
        int r = row0 + ar[i];
        int src = GATHER ? win_src_row(r) : r;
        abase[i] = (long)src * Asr + akq[i] * 8;
        bbase[i] = (long)(col0 + ar[i]) * Ksm + akq[i] * 8;
    }

    const int wid = tid >> 5, lane = tid & 31, lr = lane >> 2, lc = lane & 3;
    const int wm = wid >> 1, wn = wid & 1;
    float acc[2][8][4] = {};

    auto loadT = [&](int t) {
        int buf = t % 3;
        int k0 = t * 32;
#pragma unroll
        for (int i = 0; i < 2; i++) {
            cpa16(&As[buf][ar[i]][akq[i] * 4], A + abase[i] + k0, true);
            cpa16(&Bs[buf][ar[i]][akq[i] * 4], Wm + bbase[i] + k0, true);
        }
        cpcommit();
    };

    loadT(0);
    loadT(1);
    for (int t = 0; t < T; t++) {
        if (t + 1 < T) cpwait<1>(); else cpwait<0>();
        __syncthreads();
        if (t + 2 < T) loadT(t + 2);
        tile_mma64(As[t % 3], Bs[t % 3], acc, wm, wn, lane);
    }

#pragma unroll
    for (int mt = 0; mt < 2; mt++) {
#pragma unroll
        for (int nt = 0; nt < 8; nt++) {
            int rbase = row0 + wm * 32 + mt * 16 + lr;
            int cb = col0 + wn * 64 + nt * 8 + lc * 2;   // even
            if (cb >= Nc) continue;
#pragma unroll
            for (int half = 0; half < 2; half++) {
                int row = rbase + half * 8;
                float v0 = acc[mt][nt][half * 2] + bias[cb];
                float v1 = acc[mt][nt][half * 2 + 1] + bias[cb + 1];
                if constexpr (EPI == 0) {
                    int tq = cb / 180;
                    int rem = cb - tq * 180;
                    int hh = rem / 30, hd = rem - hh * 30;   // hd even
                    if (tq == 0) { v0 *= QSCALE; v1 *= QSCALE; }
                    int win = row >> 9, n = row & 511;
                    long idx = ((long)((win * 3 + tq) * NHEADS + hh) * NTOK + n) * HDIM + hd;
                    ((uint32_t*)CoutV)[idx >> 1] = pk(v0, v1);
                } else if constexpr (EPI == 1) {
                    int src = win_src_row(row);
                    long gi = (long)src * CC + cb;
                    int b = src >> 14;
                    uint32_t uy = ((const uint32_t*)e1)[gi >> 1];
                    float* Cf = (float*)CoutV;
                    Cf[gi]     = e0[gi]     + v0 + 0.01f * b2f(uy & 0xFFFF) * e2[b * CC + cb];
                    Cf[gi + 1] = e0[gi + 1] + v1 + 0.01f * b2f(uy >> 16)    * e2[b * CC + cb + 1];
                } else if constexpr (EPI == 2) {
                    long idx = (long)row * OS + cb;
                    ((uint32_t*)CoutV)[idx >> 1] = pk(gelu_exact(v0), gelu_exact(v1));
                } else {
                    long gi = (long)row * CC + cb;
                    float* Cf = (float*)CoutV;
                    Cf[gi]     = e0[gi]     + v0;
                    Cf[gi + 1] = e0[gi + 1] + v1;
                }
            }
        }
    }
}

// ---------------- conv1: 192->64, BN=64 (old layout), cp.async 3-stage ----------------
__global__ void __launch_bounds__(256) mma_conv1(
        const uint16_t* __restrict__ A, const uint16_t* __restrict__ Wt,
        const float* __restrict__ bias, void* __restrict__ OutV) {
    constexpr int Asr = 192;
    constexpr int KT = 6;
    constexpr int T = 27 * KT;
    __shared__ uint32_t As[3][128][20];
    __shared__ uint32_t Bs[3][64][20];
    const int tid = threadIdx.x;
    const int row0 = blockIdx.x * 128;

    int ar[2], akq[2], pd[2], ph[2], pw[2];
#pragma unroll
    for (int i = 0; i < 2; i++) {
        int id = tid + i * 256;
        ar[i] = id >> 2;
        akq[i] = id & 3;
        int p = row0 + ar[i];
        pd[i] = (p >> 10) & 15;
        ph[i] = (p >> 5) & 31;
        pw[i] = p & 31;
    }
    const int bn = tid >> 2, bkq = tid & 3;

    const int wid = tid >> 5, lane = tid & 31, lr = lane >> 2, lc = lane & 3;
    const int wm = wid >> 1, wn = wid & 1;
    float acc[2][4][4] = {};

    auto loadT = [&](int t) {
        int buf = t % 3;
        int tap = t / KT;
        int kt = t - tap * KT;
        int k0 = kt * 32;
        int kd = tap / 9 - 1;
        int r9 = tap - (kd + 1) * 9;
        int kh = r9 / 3 - 1;
        int kw = r9 - (kh + 1) * 3 - 1;
        int off = (kd << 10) + (kh << 5) + kw;
#pragma unroll
        for (int i = 0; i < 2; i++) {
            bool valid = ((unsigned)(pd[i] + kd) < 16u) &&
                         ((unsigned)(ph[i] + kh) < 32u) &&
                         ((unsigned)(pw[i] + kw) < 32u);
            const uint16_t* src = valid
                ? A + (long)(row0 + ar[i] + off) * Asr + k0 + akq[i] * 8 : A;
            cpa16(&As[buf][ar[i]][akq[i] * 4], src, valid);
        }
        cpa16(&Bs[buf][bn][bkq * 4],
              Wt + ((long)tap * 64 + bn) * 192 + k0 + bkq * 8, true);
        cpcommit();
    };

    loadT(0);
    loadT(1);
    for (int t = 0; t < T; t++) {
        if (t + 1 < T) cpwait<1>(); else cpwait<0>();
        __syncthreads();
        if (t + 2 < T) loadT(t + 2);
        tile_mma32(As[t % 3], Bs[t % 3], acc, wm, wn, lane);
    }

#pragma unroll
    for (int mt = 0; mt < 2; mt++) {
#pragma unroll
        for (int nt = 0; nt < 4; nt++) {
            int rbase = row0 + wm * 32 + mt * 16 + lr;
            int cb = wn * 32 + nt * 8 + lc * 2;   // even
#pragma unroll
            for (int half = 0; half < 2; half++) {
                int row = rbase + half * 8;
                float v0 = acc[mt][nt][half * 2];
                float v1 = acc[mt][nt][half * 2 + 1];
                v0 = gelu_exact(v0 + ((cb < 60) ? bias[cb] : 0.f));
                v1 = gelu_exact(v1 + ((cb + 1 < 60) ? bias[cb + 1] : 0.f));
                ((uint32_t*)OutV)[((long)row * 64 + cb) >> 1] = pk(v0, v1);
            }
        }
    }
}

// ---------------- conv2: 64->180, BM=128 BN=128 (tile_mma64) ----------------
__global__ void __launch_bounds__(256, 2) mma_conv2(
        const uint16_t* __restrict__ A, const uint16_t* __restrict__ Wt,
        const float* __restrict__ bias, void* __restrict__ OutV) {
    constexpr int Asr = 64;
    constexpr int T = 54;                 // 27 taps x 2 BK32
    extern __shared__ uint32_t sm[];
    uint32_t (*As)[128][20] = (uint32_t (*)[128][20])sm;
    uint32_t (*Bs)[128][20] = (uint32_t (*)[128][20])(sm + 3 * 128 * 20);
    const int tid = threadIdx.x;
    const int row0 = blockIdx.x * 128, col0 = blockIdx.y * 128;

    int ar[2], akq[2], pd[2], ph[2], pw[2];
#pragma unroll
    for (int i = 0; i < 2; i++) {
        int id = tid + i * 256;
        ar[i] = id >> 2;
        akq[i] = id & 3;
        int p = row0 + ar[i];
        pd[i] = (p >> 10) & 15;
        ph[i] = (p >> 5) & 31;
        pw[i] = p & 31;
    }

    const int wid = tid >> 5, lane = tid & 31, lr = lane >> 2, lc = lane & 3;
    const int wm = wid >> 1, wn = wid & 1;
    float acc[2][8][4] = {};

    auto loadT = [&](int t) {
        int buf = t % 3;
        int tap = t >> 1;
        int k0 = (t & 1) * 32;
        int kd = tap / 9 - 1;
        int r9 = tap - (kd + 1) * 9;
        int kh = r9 / 3 - 1;
        int kw = r9 - (kh + 1) * 3 - 1;
        int off = (kd << 10) + (kh << 5) + kw;
#pragma unroll
        for (int i = 0; i < 2; i++) {
            bool valid = ((unsigned)(pd[i] + kd) < 16u) &&
                         ((unsigned)(ph[i] + kh) < 32u) &&
                         ((unsigned)(pw[i] + kw) < 32u);
            const uint16_t* src = valid
                ? A + (long)(row0 + ar[i] + off) * Asr + k0 + akq[i] * 8 : A;
            cpa16(&As[buf][ar[i]][akq[i] * 4], src, valid);
            cpa16(&Bs[buf][ar[i]][akq[i] * 4],
                  Wt + ((long)tap * 256 + col0 + ar[i]) * 64 + k0 + akq[i] * 8, true);
        }
        cpcommit();
    };

    loadT(0);
    loadT(1);
    for (int t = 0; t < T; t++) {
        if (t + 1 < T) cpwait<1>(); else cpwait<0>();
        __syncthreads();
        if (t + 2 < T) loadT(t + 2);
        tile_mma64(As[t % 3], Bs[t % 3], acc, wm, wn, lane);
    }

#pragma unroll
    for (int mt = 0; mt < 2; mt++) {
#pragma unroll
        for (int nt = 0; nt < 8; nt++) {
            int rbase = row0 + wm * 32 + mt * 16 + lr;
            int cb = col0 + wn * 64 + nt * 8 + lc * 2;   // even
            if (cb >= CC) continue;
#pragma unroll
            for (int half = 0; half < 2; half++) {
                int row = rbase + half * 8;
                float v0 = acc[mt][nt][half * 2] + bias[cb];
                float v1 = acc[mt][nt][half * 2 + 1] + bias[cb + 1];
                ((uint32_t*)OutV)[((long)row * CC + cb) >> 1] = pk(v0, v1);
            }
        }
    }
}

// ---------------- pooled sum + channel attention ----------------
__global__ void pooled_kernel(const uint16_t* __restrict__ y2, float* __restrict__ pool) {
    int r0 = blockIdx.x * 64;
    int b = r0 >> 14;
    int c = threadIdx.x;
    if (c >= CC) return;
    float s = 0.f;
    for (int i = 0; i < 64; i++) s += b2f(y2[(long)(r0 + i) * CC + c]);
    atomicAdd(&pool[b * CC + c], s);
}

__global__ void catt_kernel(const float* __restrict__ pool,
        const float* __restrict__ caw1, const float* __restrict__ cab1,
        const float* __restrict__ caw2, const float* __restrict__ cab2,
        float* __restrict__ catt) {
    __shared__ float sq[2][8];
    int tid = threadIdx.x;
    if (tid < 12) {
        int b = tid / 6, j = tid % 6;
        float s = cab1[j];
        for (int c = 0; c < CC; c++)
            s += (pool[b * CC + c] * (1.f / LL)) * caw1[j * CC + c];
        sq[b][j] = fmaxf(s, 0.f);
    }
    __syncthreads();
    if (tid < CC) {
        for (int b = 0; b < 2; b++) {
            float s = cab2[tid];
#pragma unroll
            for (int j = 0; j < 6; j++) s += sq[b][j] * caw2[tid * 6 + j];
            catt[b * CC + tid] = 1.f / (1.f + __expf(-s));
        }
    }
}

// ---------------- bf16 MMA flash attention, register-resident softmax ----------------
__global__ void __launch_bounds__(256) attn_mma(const uint16_t* __restrict__ qkv,
        const uint16_t* __restrict__ biasQ, uint16_t* __restrict__ outp) {
    __shared__ uint32_t Qs[128 * 20];
    __shared__ uint32_t Ks[128 * 20];
    __shared__ uint32_t Vs[32 * 68];

    const int qt = blockIdx.x;
    const int win = blockIdx.y / NHEADS, hh = blockIdx.y % NHEADS;
    const uint32_t* qbu = (const uint32_t*)(qkv +
        ((long)((win * 3 + 0) * NHEADS + hh) * NTOK + qt * 128) * HDIM);
    const uint32_t* kbu = (const uint32_t*)(qkv +
        (long)((win * 3 + 1) * NHEADS + hh) * NTOK * HDIM);
    const uint16_t* vb = qkv + (long)((win * 3 + 2) * NHEADS + hh) * NTOK * HDIM;
    const uint32_t* bqu = (const uint32_t*)(biasQ + ((long)(hh * NTOK) + qt * 128) * NTOK);

    const int tid = threadIdx.x;
    const int w = tid >> 5, lane = tid & 31, g = lane >> 2, lc = lane & 3;
    const int lar = lane & 15;
    const int law = (lane >> 4) * 4;
    const int lbr = ((lane >> 4) << 3) + (lane & 7);
    const int lbw = ((lane >> 3) & 1) * 4;

    for (int idx = tid; idx < 128 * 16; idx += 256) {
        int r = idx >> 4, d = idx & 15;
        Qs[r * 20 + d] = (d < 15) ? qbu[r * 15 + d] : 0u;
    }
    __syncthreads();
    uint32_t qf[2][4];
    ldsm4(qf[0], &Qs[(w * 16 + lar) * 20 + law]);
    ldsm4(qf[1], &Qs[(w * 16 + lar) * 20 + 8 + law]);

    const int row0 = w * 16 + g;
    float m0 = -1e30f, m1 = -1e30f, l0 = 0.f, l1 = 0.f;
    float oacc[4][4] = {};

    for (int t0 = 0; t0 < NTOK; t0 += 128) {
        __syncthreads();
        for (int idx = tid; idx < 128 * 16; idx += 256) {
            int r = idx >> 4, d = idx & 15;
            Ks[r * 20 + d] = (d < 15) ? kbu[(t0 + r) * 15 + d] : 0u;
        }
        for (int idx = tid; idx < 32 * 64; idx += 256) {
            int d = idx >> 6, j = idx & 63;
            uint32_t u = 0u;
            if (d < HDIM) {
                uint32_t lo = vb[(long)(t0 + 2 * j) * HDIM + d];
                uint32_t hi = vb[(long)(t0 + 2 * j + 1) * HDIM + d];
                u = lo | (hi << 16);
            }
            Vs[d * 68 + j] = u;
        }
        __syncthreads();

        float sacc[16][4] = {};
#pragma unroll
        for (int ks = 0; ks < 2; ks++) {
#pragma unroll
            for (int p = 0; p < 8; p++) {
                uint32_t b2[4];
                ldsm4(b2, &Ks[(p * 16 + lbr) * 20 + ks * 8 + lbw]);
                mma16(sacc[p * 2],     qf[ks], b2);
                mma16(sacc[p * 2 + 1], qf[ks], b2 + 2);
            }
        }

        float pm0 = -1e30f, pm1 = -1e30f;
#pragma unroll
        for (int nt = 0; nt < 16; nt++) {
            int c0 = t0 + nt * 8 + lc * 2;
            uint32_t u0 = bqu[((long)row0 * NTOK + c0) >> 1];
            uint32_t u1 = bqu[((long)(row0 + 8) * NTOK + c0) >> 1];
            sacc[nt][0] += b2f(u0 & 0xFFFF);
            sacc[nt][1] += b2f(u0 >> 16);
            sacc[nt][2] += b2f(u1 & 0xFFFF);
            sacc[nt][3] += b2f(u1 >> 16);
            pm0 = fmaxf(pm0, fmaxf(sacc[nt][0], sacc[nt][1]));
            pm1 = fmaxf(pm1, fmaxf(sacc[nt][2], sacc[nt][3]));
        }
        pm0 = fmaxf(pm0, __shfl_xor_sync(~0u, pm0, 1));
        pm0 = fmaxf(pm0, __shfl_xor_sync(~0u, pm0, 2));
        pm1 = fmaxf(pm1, __shfl_xor_sync(~0u, pm1, 1));
        pm1 = fmaxf(pm1, __shfl_xor_sync(~0u, pm1, 2));
        float nm0 = fmaxf(m0, pm0), nm1 = fmaxf(m1, pm1);
        float f0 = __expf(m0 - nm0), f1 = __expf(m1 - nm1);
        m0 = nm0; m1 = nm1;

        float ps0 = 0.f, ps1 = 0.f;
        uint32_t pf[8][4];
#pragma unroll
        for (int k2 = 0; k2 < 8; k2++) {
            float e00 = __expf(sacc[2 * k2][0] - m0);
            float e01 = __expf(sacc[2 * k2][1] - m0);
            float e10 = __expf(sacc[2 * k2][2] - m1);
            float e11 = __expf(sacc[2 * k2][3] - m1);
            float e20 = __expf(sacc[2 * k2 + 1][0] - m0);
            float e21 = __expf(sacc[2 * k2 + 1][1] - m0);
            float e30 = __expf(sacc[2 * k2 + 1][2] - m1);
            float e31 = __expf(sacc[2 * k2 + 1][3] - m1);
            ps0 += e00 + e01 + e20 + e21;
            ps1 += e10 + e11 + e30 + e31;
            pf[k2][0] = pk(e00, e01);
            pf[k2][1] = pk(e10, e11);
            pf[k2][2] = pk(e20, e21);
            pf[k2][3] = pk(e30, e31);
        }
        ps0 += __shfl_xor_sync(~0u, ps0, 1);
        ps0 += __shfl_xor_sync(~0u, ps0, 2);
        ps1 += __shfl_xor_sync(~0u, ps1, 1);
        ps1 += __shfl_xor_sync(~0u, ps1, 2);
        l0 = l0 * f0 + ps0;
        l1 = l1 * f1 + ps1;

#pragma unroll
        for (int nt = 0; nt < 4; nt++) {
            oacc[nt][0] *= f0; oacc[nt][1] *= f0;
            oacc[nt][2] *= f1; oacc[nt][3] *= f1;
        }
#pragma unroll
        for (int k2 = 0; k2 < 8; k2++) {
            uint32_t ba[4], bb[4];
            ldsm4(ba, &Vs[lbr * 68 + k2 * 8 + lbw]);
            ldsm4(bb, &Vs[(lbr + 16) * 68 + k2 * 8 + lbw]);
            mma16(oacc[0], pf[k2], ba);
            mma16(oacc[1], pf[k2], ba + 2);
            mma16(oacc[2], pf[k2], bb);
            mma16(oacc[3], pf[k2], bb + 2);
        }
    }

    float i0 = 1.f / l0, i1 = 1.f / l1;
    uint16_t* ob = outp + (long)(win * NTOK + qt * 128 + w * 16) * CP + hh * HDIM;
#pragma unroll
    for (int nt = 0; nt < 4; nt++) {
        int c = nt * 8 + lc * 2;
        if (c < HDIM) {
            *(uint32_t*)&ob[(long)g * CP + c] = pk(oacc[nt][0] * i0, oacc[nt][1] * i0);
            *(uint32_t*)&ob[(long)(g + 8) * CP + c] = pk(oacc[nt][2] * i1, oacc[nt][3] * i1);
        }
    }
}

// ---------------- host launch (dual-stream fork/join for graph capture) ----------------
extern "C" void kernel_launch(void* const* d_in, const int* in_sizes, int n_in,
                              void* d_out, int out_size) {
    const float* x      = (const float*)d_in[0];
    const int*   rpi    = (const int*)  d_in[4];
    const float* g1     = (const float*)d_in[7];
    const float* b1     = (const float*)d_in[8];
    const float* qkv_w  = (const float*)d_in[9];
    const float* qkv_b  = (const float*)d_in[10];
    const float* rpb    = (const float*)d_in[11];
    const float* proj_w = (const float*)d_in[12];
    const float* proj_b = (const float*)d_in[13];
    const float* cw1    = (const float*)d_in[14];
    const float* cb1    = (const float*)d_in[15];
    const float* cw2    = (const float*)d_in[16];
    const float* cb2    = (const float*)d_in[17];
    const float* caw1   = (const float*)d_in[18];
    const float* cab1   = (const float*)d_in[19];
    const float* caw2   = (const float*)d_in[20];
    const float* cab2   = (const float*)d_in[21];
    const float* g2     = (const float*)d_in[22];
    const float* b2     = (const float*)d_in[23];
    const float* fc1_w  = (const float*)d_in[24];
    const float* fc1_b  = (const float*)d_in[25];
    const float* fc2_w  = (const float*)d_in[26];
    const float* fc2_b  = (const float*)d_in[27];
    float* outp = (float*)d_out;

    uint16_t *p_xn, *p_ln2, *p_ao, *p_y1, *p_y2, *p_qkv, *p_h, *p_bt;
    uint16_t *p_w1m, *p_w2m, *p_wq, *p_wp, *p_wf1, *p_wf2;
    float *p_x1, *p_pool, *p_catt;
    cudaGetSymbolAddress((void**)&p_xn,   g_xn);
    cudaGetSymbolAddress((void**)&p_ln2,  g_ln2);
    cudaGetSymbolAddress((void**)&p_ao,   g_ao);
    cudaGetSymbolAddress((void**)&p_x1,   g_x1);
    cudaGetSymbolAddress((void**)&p_y1,   g_y1);
    cudaGetSymbolAddress((void**)&p_y2,   g_y2);
    cudaGetSymbolAddress((void**)&p_qkv,  g_qkv);
    cudaGetSymbolAddress((void**)&p_h,    g_hbuf);
    cudaGetSymbolAddress((void**)&p_bt,   g_biasT);
    cudaGetSymbolAddress((void**)&p_w1m,  g_w1m);
    cudaGetSymbolAddress((void**)&p_w2m,  g_w2m);
    cudaGetSymbolAddress((void**)&p_wq,   g_wq);
    cudaGetSymbolAddress((void**)&p_wp,   g_wp);
    cudaGetSymbolAddress((void**)&p_wf1,  g_wf1);
    cudaGetSymbolAddress((void**)&p_wf2,  g_wf2);
    cudaGetSymbolAddress((void**)&p_pool, g_pool);
    cudaGetSymbolAddress((void**)&p_catt, g_catt);

    static bool attrs_set = false;
    if (!attrs_set) {
        cudaFuncSetAttribute(mma_gemm<0, true>,  cudaFuncAttributeMaxDynamicSharedMemorySize, G2_SMEM);
        cudaFuncSetAttribute(mma_gemm<1, false>, cudaFuncAttributeMaxDynamicSharedMemorySize, G2_SMEM);
        cudaFuncSetAttribute(mma_gemm<2, false>, cudaFuncAttributeMaxDynamicSharedMemorySize, G2_SMEM);
        cudaFuncSetAttribute(mma_gemm<3, false>, cudaFuncAttributeMaxDynamicSharedMemorySize, G2_SMEM);
        cudaFuncSetAttribute(mma_conv2, cudaFuncAttributeMaxDynamicSharedMemorySize, G2_SMEM);
        attrs_set = true;
    }

    // one-time side-stream + events
    static cudaStream_t s1 = nullptr;
    static cudaEvent_t evStart = nullptr, evLN1 = nullptr, evJoin = nullptr;
    if (s1 == nullptr) {
        cudaStreamCreateWithFlags(&s1, cudaStreamNonBlocking);
        cudaEventCreateWithFlags(&evStart, cudaEventDisableTiming);
        cudaEventCreateWithFlags(&evLN1, cudaEventDisableTiming);
        cudaEventCreateWithFlags(&evJoin, cudaEventDisableTiming);
    }

    // fork
    cudaEventRecord(evStart, 0);
    cudaStreamWaitEvent(s1, evStart, 0);

    // ---- side stream s1: conv/proj/mlp weight prep, then conv branch ----
    repack1_kernel<<<(27 * 64 * 192 + 255) / 256, 256, 0, s1>>>(cw1, p_w1m);
    repack2_kernel<<<(27 * 192 * 64 + 255) / 256, 256, 0, s1>>>(cw2, p_w2m);
    wpack_kernel<<<(180 * 192 + 255) / 256, 256, 0, s1>>>(proj_w, p_wp, 180, 180, 192);
    wpack_kernel<<<(720 * 192 + 255) / 256, 256, 0, s1>>>(fc1_w, p_wf1, 720, 180, 192);
    wpack_kernel<<<(180 * HIDP + 255) / 256, 256, 0, s1>>>(fc2_w, p_wf2, 180, 720, HIDP);
    zero_pool_kernel<<<1, 384, 0, s1>>>(p_pool);

    // ---- main stream: attention-path prep + LN1 ----
    wpack_kernel<<<(540 * 192 + 255) / 256, 256>>>(qkv_w, p_wq, 540, 180, 192);
    biasprep_kernel<<<512, 512>>>(rpi, rpb, p_bt);
    ln_kernel<<<LT / 8, 256>>>(x, CC, g1, b1, p_xn, CP);
    cudaEventRecord(evLN1, 0);

    // ---- s1: conv branch (needs xn) ----
    cudaStreamWaitEvent(s1, evLN1, 0);
    mma_conv1<<<LT / 128, 256, 0, s1>>>(p_xn, p_w1m, cb1, p_y1);
    mma_conv2<<<dim3(LT / 128, 2), 256, G2_SMEM, s1>>>(p_y1, p_w2m, cb2, p_y2);
    pooled_kernel<<<LT / 64, 192, 0, s1>>>(p_y2, p_pool);
    catt_kernel<<<1, 192, 0, s1>>>(p_pool, caw1, cab1, caw2, cab2, p_catt);
    cudaEventRecord(evJoin, s1);

    // ---- main stream: window attention path ----
    mma_gemm<0, true><<<dim3(LT / 128, 5), 256, G2_SMEM>>>(p_xn, CP, p_wq, qkv_b, p_qkv,
                                                  540, 192, 0, nullptr, nullptr, nullptr);
    attn_mma<<<dim3(4, NWIN * NHEADS), 256>>>(p_qkv, p_bt, p_ao);

    // join
    cudaStreamWaitEvent(0, evJoin, 0);
    mma_gemm<1, false><<<dim3(LT / 128, 2), 256, G2_SMEM>>>(p_ao, CP, p_wp, proj_b, p_x1,
                                                   180, 192, 0, x, p_y2, p_catt);

    // MLP
    ln_kernel<<<LT / 8, 256>>>(p_x1, CC, g2, b2, p_ln2, CP);
    mma_gemm<2, false><<<dim3(LT / 128, 6), 256, G2_SMEM>>>(p_ln2, CP, p_wf1, fc1_b, p_h,
                                                    720, 192, HIDP, nullptr, nullptr, nullptr);
    mma_gemm<3, false><<<dim3(LT / 128, 2), 256, G2_SMEM>>>(p_h, HIDP, p_wf2, fc2_b, outp,
                                                   180, HIDP, 0, p_x1, nullptr, nullptr);
}

// round 14
// speedup vs baseline: 1.0302x; 1.0302x over previous
#include <cuda_runtime.h>
#include <math.h>
#include <stdint.h>

// ---------------- problem constants ----------------
#define BB 2
#define CC 180
#define CP 192              // padded channel stride (multiple of 32)
#define DD 16
#define HH 32
#define WW 32
#define LL 16384            // D*H*W
#define LT 32768            // B*L
#define NHEADS 6
#define HDIM 30
#define NTOK 512
#define NWIN 64
#define HIDD 720
#define HIDP 736            // padded fc2 K (multiple of 32)
#define QSCALE 0.18257418583505537f  // 30^-0.5

// ---------------- device scratch (zero-initialized; pads never written) ----------------
__device__ uint16_t g_xn[LT * CP];              // bf16, LN1 out
__device__ uint16_t g_ln2[LT * CP];             // bf16, LN2 out
__device__ uint16_t g_ao[LT * CP];              // bf16, attention out (window order)
__device__ float    g_x1[LT * CC];              // fp32 residual
__device__ uint16_t g_y1[LT * 64];              // bf16 conv1 out (gelu'd, 64-pad)
__device__ uint16_t g_y2[LT * CC];              // bf16 conv2 out + bias
__device__ uint16_t g_qkv[NWIN * 3 * NHEADS * NTOK * HDIM];  // bf16
__device__ uint16_t g_hbuf[LT * HIDP];          // bf16 fc1 gelu out (K-pad 736)
__device__ uint16_t g_biasT[NHEADS * NTOK * NTOK]; // bf16 [h][query][key]
__device__ uint16_t g_w1m[27 * 64 * 192];       // bf16 [tap][cout64][cin192]
__device__ uint16_t g_w2m[27 * 192 * 64];       // bf16 [tap][cout192][cin64]
__device__ uint16_t g_wq[576 * 192];            // bf16 qkv_w (row-pad 576)
__device__ uint16_t g_wp[192 * 192];            // bf16 proj_w (row-pad 192)
__device__ uint16_t g_wf1[768 * 192];           // bf16 fc1_w (row-pad 768)
__device__ uint16_t g_wf2[192 * HIDP];          // bf16 fc2_w (row-pad 192)
__device__ float g_pool[2 * CC];
__device__ float g_catt[2 * CC];

// window (win, n) -> flat row b*LL + l  (bijection)
__device__ __forceinline__ int win_src_row(int r) {
    int win = r >> 9, n = r & 511;
    int sb = win >> 2, wq = win & 3;
    int b = sb >> 3, isp = sb & 7;
    int id = isp >> 2, ih = (isp >> 1) & 1, iw = isp & 1;
    int nhi = wq >> 1, nwi = wq & 1;
    int wd = n >> 6, wh = (n >> 3) & 7, ww = n & 7;
    int d = wd * 2 + id;
    int h = (nhi * 8 + wh) * 2 + ih;
    int w = (nwi * 8 + ww) * 2 + iw;
    return ((b * DD + d) * HH + h) * WW + w;
}

__device__ __forceinline__ float gelu_exact(float v) {
    return 0.5f * v * (1.f + erff(v * 0.70710678118654752f));
}

// pack two floats -> bf16x2 word (lo = first)
__device__ __forceinline__ uint32_t pk(float lo, float hi) {
    uint32_t r;
    asm("cvt.rn.bf16x2.f32 %0, %1, %2;" : "=r"(r) : "f"(hi), "f"(lo));
    return r;
}
__device__ __forceinline__ uint16_t f2b(float v) { return (uint16_t)pk(v, 0.f); }
__device__ __forceinline__ float b2f(uint32_t bits16) {
    return __int_as_float((int)(bits16 << 16));
}

__device__ __forceinline__ void mma16(float* c, const uint32_t* a, const uint32_t* b) {
    asm volatile(
        "mma.sync.aligned.m16n8k16.row.col.f32.bf16.bf16.f32 "
        "{%0,%1,%2,%3},{%4,%5,%6,%7},{%8,%9},{%0,%1,%2,%3};\n"
        : "+f"(c[0]), "+f"(c[1]), "+f"(c[2]), "+f"(c[3])
        : "r"(a[0]), "r"(a[1]), "r"(a[2]), "r"(a[3]), "r"(b[0]), "r"(b[1]));
}

// ldmatrix x4 (b16)
__device__ __forceinline__ void ldsm4(uint32_t* r, const void* p) {
    uint32_t addr = (uint32_t)__cvta_generic_to_shared(p);
    asm volatile("ldmatrix.sync.aligned.m8n8.x4.shared.b16 {%0,%1,%2,%3}, [%4];"
        : "=r"(r[0]), "=r"(r[1]), "=r"(r[2]), "=r"(r[3]) : "r"(addr));
}

// cp.async 16B, with zfill predication (sz=0 -> no memory access, zero fill)
__device__ __forceinline__ void cpa16(void* smem, const void* gmem, bool pred) {
    uint32_t s = (uint32_t)__cvta_generic_to_shared(smem);
    int sz = pred ? 16 : 0;
    asm volatile("cp.async.cg.shared.global [%0], [%1], 16, %2;\n"
                 :: "r"(s), "l"(gmem), "r"(sz));
}
__device__ __forceinline__ void cpcommit() {
    asm volatile("cp.async.commit_group;\n");
}
template <int N>
__device__ __forceinline__ void cpwait() {
    asm volatile("cp.async.wait_group %0;\n" :: "n"(N));
}

// warp tile 32x32 over BK=32
__device__ __forceinline__ void tile_mma32(const uint32_t (*As)[20], const uint32_t (*Bs)[20],
                                           float acc[2][4][4], int wm, int wn, int lane) {
    const int ar = wm * 32 + (lane & 15);
    const int aw = (lane >> 4) * 4;
    const int br = wn * 32 + ((lane >> 4) << 3) + (lane & 7);
    const int bw = ((lane >> 3) & 1) * 4;
#pragma unroll
    for (int ks = 0; ks < 2; ks++) {
        uint32_t a[2][4], b[2][4];
        ldsm4(a[0], &As[ar][ks * 8 + aw]);
        ldsm4(a[1], &As[ar + 16][ks * 8 + aw]);
        ldsm4(b[0], &Bs[br][ks * 8 + bw]);
        ldsm4(b[1], &Bs[br + 16][ks * 8 + bw]);
#pragma unroll
        for (int mt = 0; mt < 2; mt++)
#pragma unroll
            for (int p = 0; p < 2; p++) {
                mma16(acc[mt][p * 2],     a[mt], b[p]);
                mma16(acc[mt][p * 2 + 1], a[mt], b[p] + 2);
            }
    }
}

// warp tile 32x64 over BK=32 (fc1 only)
__device__ __forceinline__ void tile_mma64(const uint32_t (*As)[20], const uint32_t (*Bs)[20],
                                           float acc[2][8][4], int wm, int wn, int lane) {
    const int ar = wm * 32 + (lane & 15);
    const int aw = (lane >> 4) * 4;
    const int br = ((lane >> 4) << 3) + (lane & 7);
    const int bw = ((lane >> 3) & 1) * 4;
#pragma unroll
    for (int ks = 0; ks < 2; ks++) {
        uint32_t a[2][4], b[4][4];
        ldsm4(a[0], &As[ar][ks * 8 + aw]);
        ldsm4(a[1], &As[ar + 16][ks * 8 + aw]);
#pragma unroll
        for (int p = 0; p < 4; p++)
            ldsm4(b[p], &Bs[wn * 64 + p * 16 + br][ks * 8 + bw]);
#pragma unroll
        for (int mt = 0; mt < 2; mt++)
#pragma unroll
            for (int p = 0; p < 4; p++) {
                mma16(acc[mt][p * 2],     a[mt], b[p]);
                mma16(acc[mt][p * 2 + 1], a[mt], b[p] + 2);
            }
    }
}

#define FC1_SMEM (2 * 3 * 128 * 20 * 4)   // 61440 bytes

// ---------------- prep kernels ----------------
__global__ void wpack_kernel(const float* __restrict__ w, uint16_t* __restrict__ out,
                             int N, int K, int Ksm) {
    int idx = blockIdx.x * 256 + threadIdx.x;
    if (idx >= N * Ksm) return;
    int n = idx / Ksm, k = idx - n * Ksm;
    out[idx] = (k < K) ? f2b(w[n * K + k]) : (uint16_t)0;
}

__global__ void repack1_kernel(const float* __restrict__ cw1, uint16_t* __restrict__ w1m) {
    int idx = blockIdx.x * 256 + threadIdx.x;
    if (idx >= 27 * 64 * 192) return;
    int tap = idx / (64 * 192);
    int rem = idx - tap * 64 * 192;
    int o = rem / 192, c = rem - o * 192;
    w1m[idx] = (o < 60 && c < 180) ? f2b(cw1[(o * 180 + c) * 27 + tap]) : (uint16_t)0;
}

__global__ void repack2_kernel(const float* __restrict__ cw2, uint16_t* __restrict__ w2m) {
    int idx = blockIdx.x * 256 + threadIdx.x;
    if (idx >= 27 * 192 * 64) return;
    int tap = idx / (192 * 64);
    int rem = idx - tap * 192 * 64;
    int o = rem >> 6, c = rem & 63;
    w2m[idx] = (o < 180 && c < 60) ? f2b(cw2[(o * 60 + c) * 27 + tap]) : (uint16_t)0;
}

// bias table: [h][query][key] bf16
__global__ void biasprep_kernel(const int* __restrict__ rpi, const float* __restrict__ rpb,
                                uint16_t* __restrict__ biasT) {
    int q = blockIdx.x, k = threadIdx.x;
    int t = rpi[q * 512 + k];
#pragma unroll
    for (int h = 0; h < NHEADS; h++)
        biasT[(h * 512 + q) * 512 + k] = f2b(rpb[t * NHEADS + h]);
}

__global__ void zero_pool_kernel(float* __restrict__ pool) {
    if (threadIdx.x < 2 * CC) pool[threadIdx.x] = 0.f;
}

// ---------------- layernorm (warp per row), bf16 out ----------------
__global__ void __launch_bounds__(256) ln_kernel(const float* __restrict__ in, int ins,
        const float* __restrict__ gg, const float* __restrict__ bb,
        uint16_t* __restrict__ outp, int outs) {
    int row = blockIdx.x * 8 + (threadIdx.x >> 5);
    int lane = threadIdx.x & 31;
    const float* p = in + (long)row * ins;
    float v[6];
    float s = 0.f;
#pragma unroll
    for (int i = 0; i < 6; i++) {
        int c = lane + i * 32;
        v[i] = (c < CC) ? p[c] : 0.f;
        s += v[i];
    }
    for (int o = 16; o; o >>= 1) s += __shfl_xor_sync(~0u, s, o);
    float mean = s * (1.f / CC);
    float vs = 0.f;
#pragma unroll
    for (int i = 0; i < 6; i++) {
        int c = lane + i * 32;
        float d = (c < CC) ? (v[i] - mean) : 0.f;
        vs += d * d;
    }
    for (int o = 16; o; o >>= 1) vs += __shfl_xor_sync(~0u, vs, o);
    float inv = rsqrtf(vs * (1.f / CC) + 1e-5f);
    uint16_t* q = outp + (long)row * outs;
#pragma unroll
    for (int i = 0; i < 6; i++) {
        int c = lane + i * 32;
        if (c < CC) q[c] = f2b((v[i] - mean) * inv * gg[c] + bb[c]);
    }
}

// ---------------- bf16 MMA GEMM, BN=64, cp.async 3-stage, BK=32, fused epilogues ----------------
// EPI 0: qkv scatter bf16 (+q scale); 1: proj scatter + triple residual (e1 = bf16 y2);
//     2: gelu -> bf16 (stride OS); 3: residual -> fp32 out
template <int EPI, bool GATHER>
__global__ void __launch_bounds__(256) mma_gemm(
        const uint16_t* __restrict__ A, int Asr,
        const uint16_t* __restrict__ Wm, const float* __restrict__ bias,
        void* __restrict__ CoutV, int Nc, int Ksm, int OS,
        const float* __restrict__ e0, const uint16_t* __restrict__ e1,
        const float* __restrict__ e2) {
    __shared__ uint32_t As[3][128][20];
    __shared__ uint32_t Bs[3][64][20];
    const int tid = threadIdx.x;
    const int row0 = blockIdx.x * 128, col0 = blockIdx.y * 64;
    const int T = Ksm >> 5;

    int ar[2], akq[2];
    long abase[2];
#pragma unroll
    for (int i = 0; i < 2; i++) {
        int id = tid + i * 256;
        ar[i] = id >> 2;
        akq[i] = id & 3;
        int r = row0 + ar[i];
        int src = GATHER ? win_src_row(r) : r;
        abase[i] = (long)src * Asr + akq[i] * 8;
    }
    const int bn = tid >> 2, bkq = tid & 3;
    const long bbase = (long)(col0 + bn) * Ksm + bkq * 8;

    const int wid = tid >> 5, lane = tid & 31, lr = lane >> 2, lc = lane & 3;
    const int wm = wid >> 1, wn = wid & 1;
    float acc[2][4][4] = {};

    auto loadT = [&](int t) {
        int buf = t % 3;
        int k0 = t * 32;
#pragma unroll
        for (int i = 0; i < 2; i++)
            cpa16(&As[buf][ar[i]][akq[i] * 4], A + abase[i] + k0, true);
        cpa16(&Bs[buf][bn][bkq * 4], Wm + bbase + k0, true);
        cpcommit();
    };

    loadT(0);
    loadT(1);
    for (int t = 0; t < T; t++) {
        if (t + 1 < T) cpwait<1>(); else cpwait<0>();
        __syncthreads();
        if (t + 2 < T) loadT(t + 2);
        tile_mma32(As[t % 3], Bs[t % 3], acc, wm, wn, lane);
    }

#pragma unroll
    for (int mt = 0; mt < 2; mt++) {
#pragma unroll
        for (int nt = 0; nt < 4; nt++) {
            int rbase = row0 + wm * 32 + mt * 16 + lr;
            int cb = col0 + wn * 32 + nt * 8 + lc * 2;   // even
            if (cb >= Nc) continue;
#pragma unroll
            for (int half = 0; half < 2; half++) {
                int row = rbase + half * 8;
                float v0 = acc[mt][nt][half * 2] + bias[cb];
                float v1 = acc[mt][nt][half * 2 + 1] + bias[cb + 1];
                if constexpr (EPI == 0) {
                    int tq = cb / 180;
                    int rem = cb - tq * 180;
                    int hh = rem / 30, hd = rem - hh * 30;   // hd even
                    if (tq == 0) { v0 *= QSCALE; v1 *= QSCALE; }
                    int win = row >> 9, n = row & 511;
                    long idx = ((long)((win * 3 + tq) * NHEADS + hh) * NTOK + n) * HDIM + hd;
                    ((uint32_t*)CoutV)[idx >> 1] = pk(v0, v1);
                } else if constexpr (EPI == 1) {
                    int src = win_src_row(row);
                    long gi = (long)src * CC + cb;
                    int b = src >> 14;
                    uint32_t uy = ((const uint32_t*)e1)[gi >> 1];
                    float* Cf = (float*)CoutV;
                    Cf[gi]     = e0[gi]     + v0 + 0.01f * b2f(uy & 0xFFFF) * e2[b * CC + cb];
                    Cf[gi + 1] = e0[gi + 1] + v1 + 0.01f * b2f(uy >> 16)    * e2[b * CC + cb + 1];
                } else if constexpr (EPI == 2) {
                    long idx = (long)row * OS + cb;
                    ((uint32_t*)CoutV)[idx >> 1] = pk(gelu_exact(v0), gelu_exact(v1));
                } else {
                    long gi = (long)row * CC + cb;
                    float* Cf = (float*)CoutV;
                    Cf[gi]     = e0[gi]     + v0;
                    Cf[gi + 1] = e0[gi + 1] + v1;
                }
            }
        }
    }
}

// ---------------- fc1: BM=128 BN=128, gelu->bf16 epilogue (Nc=720, K=192) ----------------
__global__ void __launch_bounds__(256, 2) mma_fc1(
        const uint16_t* __restrict__ A, const uint16_t* __restrict__ Wm,
        const float* __restrict__ bias, uint32_t* __restrict__ Cout) {
    extern __shared__ uint32_t sm[];
    uint32_t (*As)[128][20] = (uint32_t (*)[128][20])sm;
    uint32_t (*Bs)[128][20] = (uint32_t (*)[128][20])(sm + 3 * 128 * 20);
    const int tid = threadIdx.x;
    const int row0 = blockIdx.x * 128, col0 = blockIdx.y * 128;
    const int T = 6;   // K = 192

    int ar[2], akq[2];
    long abase[2], bbase[2];
#pragma unroll
    for (int i = 0; i < 2; i++) {
        int id = tid + i * 256;
        ar[i] = id >> 2;
        akq[i] = id & 3;
        abase[i] = (long)(row0 + ar[i]) * CP + akq[i] * 8;
        bbase[i] = (long)(col0 + ar[i]) * 192 + akq[i] * 8;
    }

    const int wid = tid >> 5, lane = tid & 31, lr = lane >> 2, lc = lane & 3;
    const int wm = wid >> 1, wn = wid & 1;
    float acc[2][8][4] = {};

    auto loadT = [&](int t) {
        int buf = t % 3;
        int k0 = t * 32;
#pragma unroll
        for (int i = 0; i < 2; i++) {
            cpa16(&As[buf][ar[i]][akq[i] * 4], A + abase[i] + k0, true);
            cpa16(&Bs[buf][ar[i]][akq[i] * 4], Wm + bbase[i] + k0, true);
        }
        cpcommit();
    };

    loadT(0);
    loadT(1);
    for (int t = 0; t < T; t++) {
        if (t + 1 < T) cpwait<1>(); else cpwait<0>();
        __syncthreads();
        if (t + 2 < T) loadT(t + 2);
        tile_mma64(As[t % 3], Bs[t % 3], acc, wm, wn, lane);
    }

#pragma unroll
    for (int mt = 0; mt < 2; mt++) {
#pragma unroll
        for (int nt = 0; nt < 8; nt++) {
            int rbase = row0 + wm * 32 + mt * 16 + lr;
            int cb = col0 + wn * 64 + nt * 8 + lc * 2;   // even
            if (cb >= HIDD) continue;
#pragma unroll
            for (int half = 0; half < 2; half++) {
                int row = rbase + half * 8;
                float v0 = gelu_exact(acc[mt][nt][half * 2] + bias[cb]);
                float v1 = gelu_exact(acc[mt][nt][half * 2 + 1] + bias[cb + 1]);
                Cout[((long)row * HIDP + cb) >> 1] = pk(v0, v1);
            }
        }
    }
}

// ---------------- bf16 MMA implicit-GEMM 3x3x3 conv, cp.async 3-stage, BK=32 ----------------
// CV=2 uses col offset coff (units of 64 cols) for split-stream execution
template <int CV>
__global__ void __launch_bounds__(256) mma_conv(
        const uint16_t* __restrict__ A, const uint16_t* __restrict__ Wt,
        const float* __restrict__ bias, void* __restrict__ OutV, int coff) {
    constexpr int Asr = (CV == 1) ? 192 : 64;
    constexpr int KT = (CV == 1) ? 6 : 2;      // 32-wide k-tiles per tap
    constexpr int T = 27 * KT;
    constexpr int Wn = (CV == 1) ? 64 : 192;
    constexpr int Wk = (CV == 1) ? 192 : 64;
    __shared__ uint32_t As[3][128][20];
    __shared__ uint32_t Bs[3][64][20];
    const int tid = threadIdx.x;
    const int row0 = blockIdx.x * 128, col0 = (blockIdx.y + coff) * 64;

    int ar[2], akq[2], pd[2], ph[2], pw[2];
#pragma unroll
    for (int i = 0; i < 2; i++) {
        int id = tid + i * 256;
        ar[i] = id >> 2;
        akq[i] = id & 3;
        int p = row0 + ar[i];
        pd[i] = (p >> 10) & 15;
        ph[i] = (p >> 5) & 31;
        pw[i] = p & 31;
    }
    const int bn = tid >> 2, bkq = tid & 3;

    const int wid = tid >> 5, lane = tid & 31, lr = lane >> 2, lc = lane & 3;
    const int wm = wid >> 1, wn = wid & 1;
    float acc[2][4][4] = {};

    auto loadT = [&](int t) {
        int buf = t % 3;
        int tap = t / KT;
        int kt = t - tap * KT;
        int k0 = kt * 32;
        int kd = tap / 9 - 1;
        int r9 = tap - (kd + 1) * 9;
        int kh = r9 / 3 - 1;
        int kw = r9 - (kh + 1) * 3 - 1;
        int off = (kd << 10) + (kh << 5) + kw;
#pragma unroll
        for (int i = 0; i < 2; i++) {
            bool valid = ((unsigned)(pd[i] + kd) < 16u) &&
                         ((unsigned)(ph[i] + kh) < 32u) &&
                         ((unsigned)(pw[i] + kw) < 32u);
            const uint16_t* src = valid
                ? A + (long)(row0 + ar[i] + off) * Asr + k0 + akq[i] * 8 : A;
            cpa16(&As[buf][ar[i]][akq[i] * 4], src, valid);
        }
        cpa16(&Bs[buf][bn][bkq * 4],
              Wt + ((long)tap * Wn + col0 + bn) * Wk + k0 + bkq * 8, true);
        cpcommit();
    };

    loadT(0);
    loadT(1);
    for (int t = 0; t < T; t++) {
        if (t + 1 < T) cpwait<1>(); else cpwait<0>();
        __syncthreads();
        if (t + 2 < T) loadT(t + 2);
        tile_mma32(As[t % 3], Bs[t % 3], acc, wm, wn, lane);
    }

#pragma unroll
    for (int mt = 0; mt < 2; mt++) {
#pragma unroll
        for (int nt = 0; nt < 4; nt++) {
            int rbase = row0 + wm * 32 + mt * 16 + lr;
            int cb = col0 + wn * 32 + nt * 8 + lc * 2;   // even
#pragma unroll
            for (int half = 0; half < 2; half++) {
                int row = rbase + half * 8;
                float v0 = acc[mt][nt][half * 2];
                float v1 = acc[mt][nt][half * 2 + 1];
                if constexpr (CV == 1) {
                    v0 = gelu_exact(v0 + ((cb < 60) ? bias[cb] : 0.f));
                    v1 = gelu_exact(v1 + ((cb + 1 < 60) ? bias[cb + 1] : 0.f));
                    ((uint32_t*)OutV)[((long)row * 64 + cb) >> 1] = pk(v0, v1);
                } else {
                    if (cb < CC) {
                        ((uint32_t*)OutV)[((long)row * CC + cb) >> 1] =
                            pk(v0 + bias[cb], v1 + bias[cb + 1]);
                    }
                }
            }
        }
    }
}

// ---------------- pooled sum + channel attention ----------------
__global__ void pooled_kernel(const uint16_t* __restrict__ y2, float* __restrict__ pool) {
    int r0 = blockIdx.x * 64;
    int b = r0 >> 14;
    int c = threadIdx.x;
    if (c >= CC) return;
    float s = 0.f;
    for (int i = 0; i < 64; i++) s += b2f(y2[(long)(r0 + i) * CC + c]);
    atomicAdd(&pool[b * CC + c], s);
}

__global__ void catt_kernel(const float* __restrict__ pool,
        const float* __restrict__ caw1, const float* __restrict__ cab1,
        const float* __restrict__ caw2, const float* __restrict__ cab2,
        float* __restrict__ catt) {
    __shared__ float sq[2][8];
    int tid = threadIdx.x;
    if (tid < 12) {
        int b = tid / 6, j = tid % 6;
        float s = cab1[j];
        for (int c = 0; c < CC; c++)
            s += (pool[b * CC + c] * (1.f / LL)) * caw1[j * CC + c];
        sq[b][j] = fmaxf(s, 0.f);
    }
    __syncthreads();
    if (tid < CC) {
        for (int b = 0; b < 2; b++) {
            float s = cab2[tid];
#pragma unroll
            for (int j = 0; j < 6; j++) s += sq[b][j] * caw2[tid * 6 + j];
            catt[b * CC + tid] = 1.f / (1.f + __expf(-s));
        }
    }
}

// ---------------- bf16 MMA flash attention, register-resident softmax ----------------
__global__ void __launch_bounds__(256) attn_mma(const uint16_t* __restrict__ qkv,
        const uint16_t* __restrict__ biasQ, uint16_t* __restrict__ outp) {
    __shared__ uint32_t Qs[128 * 20];
    __shared__ uint32_t Ks[128 * 20];
    __shared__ uint32_t Vs[32 * 68];

    const int qt = blockIdx.x;
    const int win = blockIdx.y / NHEADS, hh = blockIdx.y % NHEADS;
    const uint32_t* qbu = (const uint32_t*)(qkv +
        ((long)((win * 3 + 0) * NHEADS + hh) * NTOK + qt * 128) * HDIM);
    const uint32_t* kbu = (const uint32_t*)(qkv +
        (long)((win * 3 + 1) * NHEADS + hh) * NTOK * HDIM);
    const uint16_t* vb = qkv + (long)((win * 3 + 2) * NHEADS + hh) * NTOK * HDIM;
    const uint32_t* bqu = (const uint32_t*)(biasQ + ((long)(hh * NTOK) + qt * 128) * NTOK);

    const int tid = threadIdx.x;
    const int w = tid >> 5, lane = tid & 31, g = lane >> 2, lc = lane & 3;
    const int lar = lane & 15;
    const int law = (lane >> 4) * 4;
    const int lbr = ((lane >> 4) << 3) + (lane & 7);
    const int lbw = ((lane >> 3) & 1) * 4;

    for (int idx = tid; idx < 128 * 16; idx += 256) {
        int r = idx >> 4, d = idx & 15;
        Qs[r * 20 + d] = (d < 15) ? qbu[r * 15 + d] : 0u;
    }
    __syncthreads();
    uint32_t qf[2][4];
    ldsm4(qf[0], &Qs[(w * 16 + lar) * 20 + law]);
    ldsm4(qf[1], &Qs[(w * 16 + lar) * 20 + 8 + law]);

    const int row0 = w * 16 + g;
    float m0 = -1e30f, m1 = -1e30f, l0 = 0.f, l1 = 0.f;
    float oacc[4][4] = {};

    for (int t0 = 0; t0 < NTOK; t0 += 128) {
        __syncthreads();
        for (int idx = tid; idx < 128 * 16; idx += 256) {
            int r = idx >> 4, d = idx & 15;
            Ks[r * 20 + d] = (d < 15) ? kbu[(t0 + r) * 15 + d] : 0u;
        }
        for (int idx = tid; idx < 32 * 64; idx += 256) {
            int d = idx >> 6, j = idx & 63;
            uint32_t u = 0u;
            if (d < HDIM) {
                uint32_t lo = vb[(long)(t0 + 2 * j) * HDIM + d];
                uint32_t hi = vb[(long)(t0 + 2 * j + 1) * HDIM + d];
                u = lo | (hi << 16);
            }
            Vs[d * 68 + j] = u;
        }
        __syncthreads();

        float sacc[16][4] = {};
#pragma unroll
        for (int ks = 0; ks < 2; ks++) {
#pragma unroll
            for (int p = 0; p < 8; p++) {
                uint32_t b2[4];
                ldsm4(b2, &Ks[(p * 16 + lbr) * 20 + ks * 8 + lbw]);
                mma16(sacc[p * 2],     qf[ks], b2);
                mma16(sacc[p * 2 + 1], qf[ks], b2 + 2);
            }
        }

        float pm0 = -1e30f, pm1 = -1e30f;
#pragma unroll
        for (int nt = 0; nt < 16; nt++) {
            int c0 = t0 + nt * 8 + lc * 2;
            uint32_t u0 = bqu[((long)row0 * NTOK + c0) >> 1];
            uint32_t u1 = bqu[((long)(row0 + 8) * NTOK + c0) >> 1];
            sacc[nt][0] += b2f(u0 & 0xFFFF);
            sacc[nt][1] += b2f(u0 >> 16);
            sacc[nt][2] += b2f(u1 & 0xFFFF);
            sacc[nt][3] += b2f(u1 >> 16);
            pm0 = fmaxf(pm0, fmaxf(sacc[nt][0], sacc[nt][1]));
            pm1 = fmaxf(pm1, fmaxf(sacc[nt][2], sacc[nt][3]));
        }
        pm0 = fmaxf(pm0, __shfl_xor_sync(~0u, pm0, 1));
        pm0 = fmaxf(pm0, __shfl_xor_sync(~0u, pm0, 2));
        pm1 = fmaxf(pm1, __shfl_xor_sync(~0u, pm1, 1));
        pm1 = fmaxf(pm1, __shfl_xor_sync(~0u, pm1, 2));
        float nm0 = fmaxf(m0, pm0), nm1 = fmaxf(m1, pm1);
        float f0 = __expf(m0 - nm0), f1 = __expf(m1 - nm1);
        m0 = nm0; m1 = nm1;

        float ps0 = 0.f, ps1 = 0.f;
        uint32_t pf[8][4];
#pragma unroll
        for (int k2 = 0; k2 < 8; k2++) {
            float e00 = __expf(sacc[2 * k2][0] - m0);
            float e01 = __expf(sacc[2 * k2][1] - m0);
            float e10 = __expf(sacc[2 * k2][2] - m1);
            float e11 = __expf(sacc[2 * k2][3] - m1);
            float e20 = __expf(sacc[2 * k2 + 1][0] - m0);
            float e21 = __expf(sacc[2 * k2 + 1][1] - m0);
            float e30 = __expf(sacc[2 * k2 + 1][2] - m1);
            float e31 = __expf(sacc[2 * k2 + 1][3] - m1);
            ps0 += e00 + e01 + e20 + e21;
            ps1 += e10 + e11 + e30 + e31;
            pf[k2][0] = pk(e00, e01);
            pf[k2][1] = pk(e10, e11);
            pf[k2][2] = pk(e20, e21);
            pf[k2][3] = pk(e30, e31);
        }
        ps0 += __shfl_xor_sync(~0u, ps0, 1);
        ps0 += __shfl_xor_sync(~0u, ps0, 2);
        ps1 += __shfl_xor_sync(~0u, ps1, 1);
        ps1 += __shfl_xor_sync(~0u, ps1, 2);
        l0 = l0 * f0 + ps0;
        l1 = l1 * f1 + ps1;

#pragma unroll
        for (int nt = 0; nt < 4; nt++) {
            oacc[nt][0] *= f0; oacc[nt][1] *= f0;
            oacc[nt][2] *= f1; oacc[nt][3] *= f1;
        }
#pragma unroll
        for (int k2 = 0; k2 < 8; k2++) {
            uint32_t ba[4], bb[4];
            ldsm4(ba, &Vs[lbr * 68 + k2 * 8 + lbw]);
            ldsm4(bb, &Vs[(lbr + 16) * 68 + k2 * 8 + lbw]);
            mma16(oacc[0], pf[k2], ba);
            mma16(oacc[1], pf[k2], ba + 2);
            mma16(oacc[2], pf[k2], bb);
            mma16(oacc[3], pf[k2], bb + 2);
        }
    }

    float i0 = 1.f / l0, i1 = 1.f / l1;
    uint16_t* ob = outp + (long)(win * NTOK + qt * 128 + w * 16) * CP + hh * HDIM;
#pragma unroll
    for (int nt = 0; nt < 4; nt++) {
        int c = nt * 8 + lc * 2;
        if (c < HDIM) {
            *(uint32_t*)&ob[(long)g * CP + c] = pk(oacc[nt][0] * i0, oacc[nt][1] * i0);
            *(uint32_t*)&ob[(long)(g + 8) * CP + c] = pk(oacc[nt][2] * i1, oacc[nt][3] * i1);
        }
    }
}

// ---------------- host launch (dual-stream fork/join for graph capture) ----------------
extern "C" void kernel_launch(void* const* d_in, const int* in_sizes, int n_in,
                              void* d_out, int out_size) {
    const float* x      = (const float*)d_in[0];
    const int*   rpi    = (const int*)  d_in[4];
    const float* g1     = (const float*)d_in[7];
    const float* b1     = (const float*)d_in[8];
    const float* qkv_w  = (const float*)d_in[9];
    const float* qkv_b  = (const float*)d_in[10];
    const float* rpb    = (const float*)d_in[11];
    const float* proj_w = (const float*)d_in[12];
    const float* proj_b = (const float*)d_in[13];
    const float* cw1    = (const float*)d_in[14];
    const float* cb1    = (const float*)d_in[15];
    const float* cw2    = (const float*)d_in[16];
    const float* cb2    = (const float*)d_in[17];
    const float* caw1   = (const float*)d_in[18];
    const float* cab1   = (const float*)d_in[19];
    const float* caw2   = (const float*)d_in[20];
    const float* cab2   = (const float*)d_in[21];
    const float* g2     = (const float*)d_in[22];
    const float* b2     = (const float*)d_in[23];
    const float* fc1_w  = (const float*)d_in[24];
    const float* fc1_b  = (const float*)d_in[25];
    const float* fc2_w  = (const float*)d_in[26];
    const float* fc2_b  = (const float*)d_in[27];
    float* outp = (float*)d_out;

    uint16_t *p_xn, *p_ln2, *p_ao, *p_y1, *p_y2, *p_qkv, *p_h, *p_bt;
    uint16_t *p_w1m, *p_w2m, *p_wq, *p_wp, *p_wf1, *p_wf2;
    float *p_x1, *p_pool, *p_catt;
    cudaGetSymbolAddress((void**)&p_xn,   g_xn);
    cudaGetSymbolAddress((void**)&p_ln2,  g_ln2);
    cudaGetSymbolAddress((void**)&p_ao,   g_ao);
    cudaGetSymbolAddress((void**)&p_x1,   g_x1);
    cudaGetSymbolAddress((void**)&p_y1,   g_y1);
    cudaGetSymbolAddress((void**)&p_y2,   g_y2);
    cudaGetSymbolAddress((void**)&p_qkv,  g_qkv);
    cudaGetSymbolAddress((void**)&p_h,    g_hbuf);
    cudaGetSymbolAddress((void**)&p_bt,   g_biasT);
    cudaGetSymbolAddress((void**)&p_w1m,  g_w1m);
    cudaGetSymbolAddress((void**)&p_w2m,  g_w2m);
    cudaGetSymbolAddress((void**)&p_wq,   g_wq);
    cudaGetSymbolAddress((void**)&p_wp,   g_wp);
    cudaGetSymbolAddress((void**)&p_wf1,  g_wf1);
    cudaGetSymbolAddress((void**)&p_wf2,  g_wf2);
    cudaGetSymbolAddress((void**)&p_pool, g_pool);
    cudaGetSymbolAddress((void**)&p_catt, g_catt);

    static bool attrs_set = false;
    if (!attrs_set) {
        cudaFuncSetAttribute(mma_fc1, cudaFuncAttributeMaxDynamicSharedMemorySize, FC1_SMEM);
        attrs_set = true;
    }

    // one-time side-stream + events
    static cudaStream_t s1 = nullptr;
    static cudaEvent_t evStart = nullptr, evLN1 = nullptr, evC1 = nullptr,
                       evC2m = nullptr, evJoin = nullptr;
    if (s1 == nullptr) {
        cudaStreamCreateWithFlags(&s1, cudaStreamNonBlocking);
        cudaEventCreateWithFlags(&evStart, cudaEventDisableTiming);
        cudaEventCreateWithFlags(&evLN1, cudaEventDisableTiming);
        cudaEventCreateWithFlags(&evC1, cudaEventDisableTiming);
        cudaEventCreateWithFlags(&evC2m, cudaEventDisableTiming);
        cudaEventCreateWithFlags(&evJoin, cudaEventDisableTiming);
    }

    // fork
    cudaEventRecord(evStart, 0);
    cudaStreamWaitEvent(s1, evStart, 0);

    // ---- side stream s1: conv/proj/mlp weight prep ----
    repack1_kernel<<<(27 * 64 * 192 + 255) / 256, 256, 0, s1>>>(cw1, p_w1m);
    repack2_kernel<<<(27 * 192 * 64 + 255) / 256, 256, 0, s1>>>(cw2, p_w2m);
    wpack_kernel<<<(180 * 192 + 255) / 256, 256, 0, s1>>>(proj_w, p_wp, 180, 180, 192);
    wpack_kernel<<<(720 * 192 + 255) / 256, 256, 0, s1>>>(fc1_w, p_wf1, 720, 180, 192);
    wpack_kernel<<<(180 * HIDP + 255) / 256, 256, 0, s1>>>(fc2_w, p_wf2, 180, 720, HIDP);
    zero_pool_kernel<<<1, 384, 0, s1>>>(p_pool);

    // ---- main stream: attention-path prep + LN1 ----
    wpack_kernel<<<(540 * 192 + 255) / 256, 256>>>(qkv_w, p_wq, 540, 180, 192);
    biasprep_kernel<<<512, 512>>>(rpi, rpb, p_bt);
    ln_kernel<<<LT / 8, 256>>>(x, CC, g1, b1, p_xn, CP);
    cudaEventRecord(evLN1, 0);

    // ---- s1: conv branch (needs xn); conv2 cols 0..127 ----
    cudaStreamWaitEvent(s1, evLN1, 0);
    mma_conv<1><<<LT / 128, 256, 0, s1>>>(p_xn, p_w1m, cb1, p_y1, 0);
    cudaEventRecord(evC1, s1);
    mma_conv<2><<<dim3(LT / 128, 2), 256, 0, s1>>>(p_y1, p_w2m, cb2, p_y2, 0);

    // ---- main stream: qkv + attention, then conv2 cols 128..191 ----
    mma_gemm<0, true><<<dim3(LT / 128, 9), 256>>>(p_xn, CP, p_wq, qkv_b, p_qkv,
                                                  540, 192, 0, nullptr, nullptr, nullptr);
    attn_mma<<<dim3(4, NWIN * NHEADS), 256>>>(p_qkv, p_bt, p_ao);
    cudaStreamWaitEvent(0, evC1, 0);
    mma_conv<2><<<dim3(LT / 128, 1), 256>>>(p_y1, p_w2m, cb2, p_y2, 2);
    cudaEventRecord(evC2m, 0);

    // ---- s1: pooled + catt (needs all y2 parts) ----
    cudaStreamWaitEvent(s1, evC2m, 0);
    pooled_kernel<<<LT / 64, 192, 0, s1>>>(p_y2, p_pool);
    catt_kernel<<<1, 192, 0, s1>>>(p_pool, caw1, cab1, caw2, cab2, p_catt);
    cudaEventRecord(evJoin, s1);

    // join: proj needs y2 + catt
    cudaStreamWaitEvent(0, evJoin, 0);
    mma_gemm<1, false><<<dim3(LT / 128, 3), 256>>>(p_ao, CP, p_wp, proj_b, p_x1,
                                                   180, 192, 0, x, p_y2, p_catt);

    // MLP
    ln_kernel<<<LT / 8, 256>>>(p_x1, CC, g2, b2, p_ln2, CP);
    mma_fc1<<<dim3(LT / 128, 6), 256, FC1_SMEM>>>(p_ln2, p_wf1, fc1_b, (uint32_t*)p_h);
    mma_gemm<3, false><<<dim3(LT / 128, 3), 256>>>(p_h, HIDP, p_wf2, fc2_b, outp,
                                                   180, HIDP, 0, p_x1, nullptr, nullptr);
}

// round 15
// speedup vs baseline: 1.0374x; 1.0070x over previous
#include <cuda_runtime.h>
#include <math.h>
#include <stdint.h>

// ---------------- problem constants ----------------
#define BB 2
#define CC 180
#define CP 192              // padded channel stride (multiple of 32)
#define DD 16
#define HH 32
#define WW 32
#define LL 16384            // D*H*W
#define LT 32768            // B*L
#define NHEADS 6
#define HDIM 30
#define NTOK 512
#define NWIN 64
#define HIDD 720
#define HIDP 736            // padded fc2 K (multiple of 32)
#define QSCALE 0.18257418583505537f  // 30^-0.5

// ---------------- device scratch (zero-initialized; pads never written) ----------------
__device__ uint16_t g_xn[LT * CP];              // bf16, LN1 out
__device__ uint16_t g_ln2[LT * CP];             // bf16, LN2 out
__device__ uint16_t g_ao[LT * CP];              // bf16, attention out (window order)
__device__ float    g_x1[LT * CC];              // fp32 residual
__device__ uint16_t g_y1[LT * 64];              // bf16 conv1 out (gelu'd, 64-pad)
__device__ uint16_t g_y2[LT * CC];              // bf16 conv2 out + bias
__device__ uint16_t g_qkv[NWIN * 3 * NHEADS * NTOK * HDIM];  // bf16
__device__ uint16_t g_hbuf[LT * HIDP];          // bf16 fc1 gelu out (K-pad 736)
__device__ uint16_t g_biasT[NHEADS * NTOK * NTOK]; // bf16 [h][query][key]
__device__ uint16_t g_w1m[27 * 64 * 192];       // bf16 [tap][cout64][cin192]
__device__ uint16_t g_w2m[27 * 192 * 64];       // bf16 [tap][cout192][cin64]
__device__ uint16_t g_wq[576 * 192];            // bf16 qkv_w (row-pad 576)
__device__ uint16_t g_wp[192 * 192];            // bf16 proj_w (row-pad 192)
__device__ uint16_t g_wf1[768 * 192];           // bf16 fc1_w (row-pad 768)
__device__ uint16_t g_wf2[192 * HIDP];          // bf16 fc2_w (row-pad 192)
__device__ float g_pool[2 * CC];
__device__ float g_catt[2 * CC];

// window (win, n) -> flat row b*LL + l  (bijection)
__device__ __forceinline__ int win_src_row(int r) {
    int win = r >> 9, n = r & 511;
    int sb = win >> 2, wq = win & 3;
    int b = sb >> 3, isp = sb & 7;
    int id = isp >> 2, ih = (isp >> 1) & 1, iw = isp & 1;
    int nhi = wq >> 1, nwi = wq & 1;
    int wd = n >> 6, wh = (n >> 3) & 7, ww = n & 7;
    int d = wd * 2 + id;
    int h = (nhi * 8 + wh) * 2 + ih;
    int w = (nwi * 8 + ww) * 2 + iw;
    return ((b * DD + d) * HH + h) * WW + w;
}

__device__ __forceinline__ float gelu_exact(float v) {
    return 0.5f * v * (1.f + erff(v * 0.70710678118654752f));
}

// pack two floats -> bf16x2 word (lo = first)
__device__ __forceinline__ uint32_t pk(float lo, float hi) {
    uint32_t r;
    asm("cvt.rn.bf16x2.f32 %0, %1, %2;" : "=r"(r) : "f"(hi), "f"(lo));
    return r;
}
__device__ __forceinline__ uint16_t f2b(float v) { return (uint16_t)pk(v, 0.f); }
__device__ __forceinline__ float b2f(uint32_t bits16) {
    return __int_as_float((int)(bits16 << 16));
}

__device__ __forceinline__ void mma16(float* c, const uint32_t* a, const uint32_t* b) {
    asm volatile(
        "mma.sync.aligned.m16n8k16.row.col.f32.bf16.bf16.f32 "
        "{%0,%1,%2,%3},{%4,%5,%6,%7},{%8,%9},{%0,%1,%2,%3};\n"
        : "+f"(c[0]), "+f"(c[1]), "+f"(c[2]), "+f"(c[3])
        : "r"(a[0]), "r"(a[1]), "r"(a[2]), "r"(a[3]), "r"(b[0]), "r"(b[1]));
}

// ldmatrix x4 (b16)
__device__ __forceinline__ void ldsm4(uint32_t* r, const void* p) {
    uint32_t addr = (uint32_t)__cvta_generic_to_shared(p);
    asm volatile("ldmatrix.sync.aligned.m8n8.x4.shared.b16 {%0,%1,%2,%3}, [%4];"
        : "=r"(r[0]), "=r"(r[1]), "=r"(r[2]), "=r"(r[3]) : "r"(addr));
}

// cp.async 16B, with zfill predication (sz=0 -> no memory access, zero fill)
__device__ __forceinline__ void cpa16(void* smem, const void* gmem, bool pred) {
    uint32_t s = (uint32_t)__cvta_generic_to_shared(smem);
    int sz = pred ? 16 : 0;
    asm volatile("cp.async.cg.shared.global [%0], [%1], 16, %2;\n"
                 :: "r"(s), "l"(gmem), "r"(sz));
}
__device__ __forceinline__ void cpcommit() {
    asm volatile("cp.async.commit_group;\n");
}
template <int N>
__device__ __forceinline__ void cpwait() {
    asm volatile("cp.async.wait_group %0;\n" :: "n"(N));
}

// warp tile 32x32 over BK=32
__device__ __forceinline__ void tile_mma32(const uint32_t (*As)[20], const uint32_t (*Bs)[20],
                                           float acc[2][4][4], int wm, int wn, int lane) {
    const int ar = wm * 32 + (lane & 15);
    const int aw = (lane >> 4) * 4;
    const int br = wn * 32 + ((lane >> 4) << 3) + (lane & 7);
    const int bw = ((lane >> 3) & 1) * 4;
#pragma unroll
    for (int ks = 0; ks < 2; ks++) {
        uint32_t a[2][4], b[2][4];
        ldsm4(a[0], &As[ar][ks * 8 + aw]);
        ldsm4(a[1], &As[ar + 16][ks * 8 + aw]);
        ldsm4(b[0], &Bs[br][ks * 8 + bw]);
        ldsm4(b[1], &Bs[br + 16][ks * 8 + bw]);
#pragma unroll
        for (int mt = 0; mt < 2; mt++)
#pragma unroll
            for (int p = 0; p < 2; p++) {
                mma16(acc[mt][p * 2],     a[mt], b[p]);
                mma16(acc[mt][p * 2 + 1], a[mt], b[p] + 2);
            }
    }
}

// warp tile 32x64 over BK=32 (fc1 only)
__device__ __forceinline__ void tile_mma64(const uint32_t (*As)[20], const uint32_t (*Bs)[20],
                                           float acc[2][8][4], int wm, int wn, int lane) {
    const int ar = wm * 32 + (lane & 15);
    const int aw = (lane >> 4) * 4;
    const int br = ((lane >> 4) << 3) + (lane & 7);
    const int bw = ((lane >> 3) & 1) * 4;
#pragma unroll
    for (int ks = 0; ks < 2; ks++) {
        uint32_t a[2][4], b[4][4];
        ldsm4(a[0], &As[ar][ks * 8 + aw]);
        ldsm4(a[1], &As[ar + 16][ks * 8 + aw]);
#pragma unroll
        for (int p = 0; p < 4; p++)
            ldsm4(b[p], &Bs[wn * 64 + p * 16 + br][ks * 8 + bw]);
#pragma unroll
        for (int mt = 0; mt < 2; mt++)
#pragma unroll
            for (int p = 0; p < 4; p++) {
                mma16(acc[mt][p * 2],     a[mt], b[p]);
                mma16(acc[mt][p * 2 + 1], a[mt], b[p] + 2);
            }
    }
}

#define FC1_SMEM (2 * 3 * 128 * 20 * 4)   // 61440 bytes

// ---------------- prep kernels ----------------
__global__ void wpack_kernel(const float* __restrict__ w, uint16_t* __restrict__ out,
                             int N, int K, int Ksm) {
    int idx = blockIdx.x * 256 + threadIdx.x;
    if (idx >= N * Ksm) return;
    int n = idx / Ksm, k = idx - n * Ksm;
    out[idx] = (k < K) ? f2b(w[n * K + k]) : (uint16_t)0;
}

__global__ void repack1_kernel(const float* __restrict__ cw1, uint16_t* __restrict__ w1m) {
    int idx = blockIdx.x * 256 + threadIdx.x;
    if (idx >= 27 * 64 * 192) return;
    int tap = idx / (64 * 192);
    int rem = idx - tap * 64 * 192;
    int o = rem / 192, c = rem - o * 192;
    w1m[idx] = (o < 60 && c < 180) ? f2b(cw1[(o * 180 + c) * 27 + tap]) : (uint16_t)0;
}

__global__ void repack2_kernel(const float* __restrict__ cw2, uint16_t* __restrict__ w2m) {
    int idx = blockIdx.x * 256 + threadIdx.x;
    if (idx >= 27 * 192 * 64) return;
    int tap = idx / (192 * 64);
    int rem = idx - tap * 192 * 64;
    int o = rem >> 6, c = rem & 63;
    w2m[idx] = (o < 180 && c < 60) ? f2b(cw2[(o * 60 + c) * 27 + tap]) : (uint16_t)0;
}

// bias table: [h][query][key] bf16
__global__ void biasprep_kernel(const int* __restrict__ rpi, const float* __restrict__ rpb,
                                uint16_t* __restrict__ biasT) {
    int q = blockIdx.x, k = threadIdx.x;
    int t = rpi[q * 512 + k];
#pragma unroll
    for (int h = 0; h < NHEADS; h++)
        biasT[(h * 512 + q) * 512 + k] = f2b(rpb[t * NHEADS + h]);
}

__global__ void zero_pool_kernel(float* __restrict__ pool) {
    if (threadIdx.x < 2 * CC) pool[threadIdx.x] = 0.f;
}

// ---------------- layernorm (warp per row), bf16 out ----------------
__global__ void __launch_bounds__(256) ln_kernel(const float* __restrict__ in, int ins,
        const float* __restrict__ gg, const float* __restrict__ bb,
        uint16_t* __restrict__ outp, int outs) {
    int row = blockIdx.x * 8 + (threadIdx.x >> 5);
    int lane = threadIdx.x & 31;
    const float* p = in + (long)row * ins;
    float v[6];
    float s = 0.f;
#pragma unroll
    for (int i = 0; i < 6; i++) {
        int c = lane + i * 32;
        v[i] = (c < CC) ? p[c] : 0.f;
        s += v[i];
    }
    for (int o = 16; o; o >>= 1) s += __shfl_xor_sync(~0u, s, o);
    float mean = s * (1.f / CC);
    float vs = 0.f;
#pragma unroll
    for (int i = 0; i < 6; i++) {
        int c = lane + i * 32;
        float d = (c < CC) ? (v[i] - mean) : 0.f;
        vs += d * d;
    }
    for (int o = 16; o; o >>= 1) vs += __shfl_xor_sync(~0u, vs, o);
    float inv = rsqrtf(vs * (1.f / CC) + 1e-5f);
    uint16_t* q = outp + (long)row * outs;
#pragma unroll
    for (int i = 0; i < 6; i++) {
        int c = lane + i * 32;
        if (c < CC) q[c] = f2b((v[i] - mean) * inv * gg[c] + bb[c]);
    }
}

// ---------------- bf16 MMA GEMM, BN=64, cp.async 3-stage, BK=32, fused epilogues ----------------
// EPI 0: qkv scatter bf16 (+q scale); 1: proj scatter + triple residual (e1 = bf16 y2);
//     2: gelu -> bf16 (stride OS); 3: residual -> fp32 out
template <int EPI, bool GATHER>
__global__ void __launch_bounds__(256) mma_gemm(
        const uint16_t* __restrict__ A, int Asr,
        const uint16_t* __restrict__ Wm, const float* __restrict__ bias,
        void* __restrict__ CoutV, int Nc, int Ksm, int OS,
        const float* __restrict__ e0, const uint16_t* __restrict__ e1,
        const float* __restrict__ e2) {
    __shared__ uint32_t As[3][128][20];
    __shared__ uint32_t Bs[3][64][20];
    const int tid = threadIdx.x;
    const int row0 = blockIdx.x * 128, col0 = blockIdx.y * 64;
    const int T = Ksm >> 5;

    int ar[2], akq[2];
    long abase[2];
#pragma unroll
    for (int i = 0; i < 2; i++) {
        int id = tid + i * 256;
        ar[i] = id >> 2;
        akq[i] = id & 3;
        int r = row0 + ar[i];
        int src = GATHER ? win_src_row(r) : r;
        abase[i] = (long)src * Asr + akq[i] * 8;
    }
    const int bn = tid >> 2, bkq = tid & 3;
    const long bbase = (long)(col0 + bn) * Ksm + bkq * 8;

    const int wid = tid >> 5, lane = tid & 31, lr = lane >> 2, lc = lane & 3;
    const int wm = wid >> 1, wn = wid & 1;
    float acc[2][4][4] = {};

    auto loadT = [&](int t) {
        int buf = t % 3;
        int k0 = t * 32;
#pragma unroll
        for (int i = 0; i < 2; i++)
            cpa16(&As[buf][ar[i]][akq[i] * 4], A + abase[i] + k0, true);
        cpa16(&Bs[buf][bn][bkq * 4], Wm + bbase + k0, true);
        cpcommit();
    };

    loadT(0);
    loadT(1);
    for (int t = 0; t < T; t++) {
        if (t + 1 < T) cpwait<1>(); else cpwait<0>();
        __syncthreads();
        if (t + 2 < T) loadT(t + 2);
        tile_mma32(As[t % 3], Bs[t % 3], acc, wm, wn, lane);
    }

#pragma unroll
    for (int mt = 0; mt < 2; mt++) {
#pragma unroll
        for (int nt = 0; nt < 4; nt++) {
            int rbase = row0 + wm * 32 + mt * 16 + lr;
            int cb = col0 + wn * 32 + nt * 8 + lc * 2;   // even
            if (cb >= Nc) continue;
#pragma unroll
            for (int half = 0; half < 2; half++) {
                int row = rbase + half * 8;
                float v0 = acc[mt][nt][half * 2] + bias[cb];
                float v1 = acc[mt][nt][half * 2 + 1] + bias[cb + 1];
                if constexpr (EPI == 0) {
                    int tq = cb / 180;
                    int rem = cb - tq * 180;
                    int hh = rem / 30, hd = rem - hh * 30;   // hd even
                    if (tq == 0) { v0 *= QSCALE; v1 *= QSCALE; }
                    int win = row >> 9, n = row & 511;
                    long idx = ((long)((win * 3 + tq) * NHEADS + hh) * NTOK + n) * HDIM + hd;
                    ((uint32_t*)CoutV)[idx >> 1] = pk(v0, v1);
                } else if constexpr (EPI == 1) {
                    int src = win_src_row(row);
                    long gi = (long)src * CC + cb;
                    int b = src >> 14;
                    uint32_t uy = ((const uint32_t*)e1)[gi >> 1];
                    float* Cf = (float*)CoutV;
                    Cf[gi]     = e0[gi]     + v0 + 0.01f * b2f(uy & 0xFFFF) * e2[b * CC + cb];
                    Cf[gi + 1] = e0[gi + 1] + v1 + 0.01f * b2f(uy >> 16)    * e2[b * CC + cb + 1];
                } else if constexpr (EPI == 2) {
                    long idx = (long)row * OS + cb;
                    ((uint32_t*)CoutV)[idx >> 1] = pk(gelu_exact(v0), gelu_exact(v1));
                } else {
                    long gi = (long)row * CC + cb;
                    float* Cf = (float*)CoutV;
                    Cf[gi]     = e0[gi]     + v0;
                    Cf[gi + 1] = e0[gi + 1] + v1;
                }
            }
        }
    }
}

// ---------------- fc1: BM=128 BN=128, gelu->bf16 epilogue (Nc=720, K=192) ----------------
__global__ void __launch_bounds__(256, 2) mma_fc1(
        const uint16_t* __restrict__ A, const uint16_t* __restrict__ Wm,
        const float* __restrict__ bias, uint32_t* __restrict__ Cout) {
    extern __shared__ uint32_t sm[];
    uint32_t (*As)[128][20] = (uint32_t (*)[128][20])sm;
    uint32_t (*Bs)[128][20] = (uint32_t (*)[128][20])(sm + 3 * 128 * 20);
    const int tid = threadIdx.x;
    const int row0 = blockIdx.x * 128, col0 = blockIdx.y * 128;
    const int T = 6;   // K = 192

    int ar[2], akq[2];
    long abase[2], bbase[2];
#pragma unroll
    for (int i = 0; i < 2; i++) {
        int id = tid + i * 256;
        ar[i] = id >> 2;
        akq[i] = id & 3;
        abase[i] = (long)(row0 + ar[i]) * CP + akq[i] * 8;
        bbase[i] = (long)(col0 + ar[i]) * 192 + akq[i] * 8;
    }

    const int wid = tid >> 5, lane = tid & 31, lr = lane >> 2, lc = lane & 3;
    const int wm = wid >> 1, wn = wid & 1;
    float acc[2][8][4] = {};

    auto loadT = [&](int t) {
        int buf = t % 3;
        int k0 = t * 32;
#pragma unroll
        for (int i = 0; i < 2; i++) {
            cpa16(&As[buf][ar[i]][akq[i] * 4], A + abase[i] + k0, true);
            cpa16(&Bs[buf][ar[i]][akq[i] * 4], Wm + bbase[i] + k0, true);
        }
        cpcommit();
    };

    loadT(0);
    loadT(1);
    for (int t = 0; t < T; t++) {
        if (t + 1 < T) cpwait<1>(); else cpwait<0>();
        __syncthreads();
        if (t + 2 < T) loadT(t + 2);
        tile_mma64(As[t % 3], Bs[t % 3], acc, wm, wn, lane);
    }

#pragma unroll
    for (int mt = 0; mt < 2; mt++) {
#pragma unroll
        for (int nt = 0; nt < 8; nt++) {
            int rbase = row0 + wm * 32 + mt * 16 + lr;
            int cb = col0 + wn * 64 + nt * 8 + lc * 2;   // even
            if (cb >= HIDD) continue;
#pragma unroll
            for (int half = 0; half < 2; half++) {
                int row = rbase + half * 8;
                float v0 = gelu_exact(acc[mt][nt][half * 2] + bias[cb]);
                float v1 = gelu_exact(acc[mt][nt][half * 2 + 1] + bias[cb + 1]);
                Cout[((long)row * HIDP + cb) >> 1] = pk(v0, v1);
            }
        }
    }
}

// ---------------- bf16 MMA implicit-GEMM 3x3x3 conv, cp.async 3-stage, BK=32 ----------------
template <int CV>
__global__ void __launch_bounds__(256) mma_conv(
        const uint16_t* __restrict__ A, const uint16_t* __restrict__ Wt,
        const float* __restrict__ bias, void* __restrict__ OutV) {
    constexpr int Asr = (CV == 1) ? 192 : 64;
    constexpr int KT = (CV == 1) ? 6 : 2;      // 32-wide k-tiles per tap
    constexpr int T = 27 * KT;
    constexpr int Wn = (CV == 1) ? 64 : 192;
    constexpr int Wk = (CV == 1) ? 192 : 64;
    __shared__ uint32_t As[3][128][20];
    __shared__ uint32_t Bs[3][64][20];
    const int tid = threadIdx.x;
    const int row0 = blockIdx.x * 128, col0 = blockIdx.y * 64;

    int ar[2], akq[2], pd[2], ph[2], pw[2];
#pragma unroll
    for (int i = 0; i < 2; i++) {
        int id = tid + i * 256;
        ar[i] = id >> 2;
        akq[i] = id & 3;
        int p = row0 + ar[i];
        pd[i] = (p >> 10) & 15;
        ph[i] = (p >> 5) & 31;
        pw[i] = p & 31;
    }
    const int bn = tid >> 2, bkq = tid & 3;

    const int wid = tid >> 5, lane = tid & 31, lr = lane >> 2, lc = lane & 3;
    const int wm = wid >> 1, wn = wid & 1;
    float acc[2][4][4] = {};

    auto loadT = [&](int t) {
        int buf = t % 3;
        int tap = t / KT;
        int kt = t - tap * KT;
        int k0 = kt * 32;
        int kd = tap / 9 - 1;
        int r9 = tap - (kd + 1) * 9;
        int kh = r9 / 3 - 1;
        int kw = r9 - (kh + 1) * 3 - 1;
        int off = (kd << 10) + (kh << 5) + kw;
#pragma unroll
        for (int i = 0; i < 2; i++) {
            bool valid = ((unsigned)(pd[i] + kd) < 16u) &&
                         ((unsigned)(ph[i] + kh) < 32u) &&
                         ((unsigned)(pw[i] + kw) < 32u);
            const uint16_t* src = valid
                ? A + (long)(row0 + ar[i] + off) * Asr + k0 + akq[i] * 8 : A;
            cpa16(&As[buf][ar[i]][akq[i] * 4], src, valid);
        }
        cpa16(&Bs[buf][bn][bkq * 4],
              Wt + ((long)tap * Wn + col0 + bn) * Wk + k0 + bkq * 8, true);
        cpcommit();
    };

    loadT(0);
    loadT(1);
    for (int t = 0; t < T; t++) {
        if (t + 1 < T) cpwait<1>(); else cpwait<0>();
        __syncthreads();
        if (t + 2 < T) loadT(t + 2);
        tile_mma32(As[t % 3], Bs[t % 3], acc, wm, wn, lane);
    }

#pragma unroll
    for (int mt = 0; mt < 2; mt++) {
#pragma unroll
        for (int nt = 0; nt < 4; nt++) {
            int rbase = row0 + wm * 32 + mt * 16 + lr;
            int cb = col0 + wn * 32 + nt * 8 + lc * 2;   // even
#pragma unroll
            for (int half = 0; half < 2; half++) {
                int row = rbase + half * 8;
                float v0 = acc[mt][nt][half * 2];
                float v1 = acc[mt][nt][half * 2 + 1];
                if constexpr (CV == 1) {
                    v0 = gelu_exact(v0 + ((cb < 60) ? bias[cb] : 0.f));
                    v1 = gelu_exact(v1 + ((cb + 1 < 60) ? bias[cb + 1] : 0.f));
                    ((uint32_t*)OutV)[((long)row * 64 + cb) >> 1] = pk(v0, v1);
                } else {
                    if (cb < CC) {
                        ((uint32_t*)OutV)[((long)row * CC + cb) >> 1] =
                            pk(v0 + bias[cb], v1 + bias[cb + 1]);
                    }
                }
            }
        }
    }
}

// ---------------- pooled sum + channel attention ----------------
__global__ void pooled_kernel(const uint16_t* __restrict__ y2, float* __restrict__ pool) {
    int r0 = blockIdx.x * 64;
    int b = r0 >> 14;
    int c = threadIdx.x;
    if (c >= CC) return;
    float s = 0.f;
    for (int i = 0; i < 64; i++) s += b2f(y2[(long)(r0 + i) * CC + c]);
    atomicAdd(&pool[b * CC + c], s);
}

__global__ void catt_kernel(const float* __restrict__ pool,
        const float* __restrict__ caw1, const float* __restrict__ cab1,
        const float* __restrict__ caw2, const float* __restrict__ cab2,
        float* __restrict__ catt) {
    __shared__ float sq[2][8];
    int tid = threadIdx.x;
    if (tid < 12) {
        int b = tid / 6, j = tid % 6;
        float s = cab1[j];
        for (int c = 0; c < CC; c++)
            s += (pool[b * CC + c] * (1.f / LL)) * caw1[j * CC + c];
        sq[b][j] = fmaxf(s, 0.f);
    }
    __syncthreads();
    if (tid < CC) {
        for (int b = 0; b < 2; b++) {
            float s = cab2[tid];
#pragma unroll
            for (int j = 0; j < 6; j++) s += sq[b][j] * caw2[tid * 6 + j];
            catt[b * CC + tid] = 1.f / (1.f + __expf(-s));
        }
    }
}

// ---------------- bf16 MMA flash attention, register-resident softmax ----------------
__global__ void __launch_bounds__(256) attn_mma(const uint16_t* __restrict__ qkv,
        const uint16_t* __restrict__ biasQ, uint16_t* __restrict__ outp) {
    __shared__ uint32_t Qs[128 * 20];
    __shared__ uint32_t Ks[128 * 20];
    __shared__ uint32_t Vs[32 * 68];

    const int qt = blockIdx.x;
    const int win = blockIdx.y / NHEADS, hh = blockIdx.y % NHEADS;
    const uint32_t* qbu = (const uint32_t*)(qkv +
        ((long)((win * 3 + 0) * NHEADS + hh) * NTOK + qt * 128) * HDIM);
    const uint32_t* kbu = (const uint32_t*)(qkv +
        (long)((win * 3 + 1) * NHEADS + hh) * NTOK * HDIM);
    const uint16_t* vb = qkv + (long)((win * 3 + 2) * NHEADS + hh) * NTOK * HDIM;
    const uint32_t* bqu = (const uint32_t*)(biasQ + ((long)(hh * NTOK) + qt * 128) * NTOK);

    const int tid = threadIdx.x;
    const int w = tid >> 5, lane = tid & 31, g = lane >> 2, lc = lane & 3;
    const int lar = lane & 15;
    const int law = (lane >> 4) * 4;
    const int lbr = ((lane >> 4) << 3) + (lane & 7);
    const int lbw = ((lane >> 3) & 1) * 4;

    for (int idx = tid; idx < 128 * 16; idx += 256) {
        int r = idx >> 4, d = idx & 15;
        Qs[r * 20 + d] = (d < 15) ? qbu[r * 15 + d] : 0u;
    }
    __syncthreads();
    uint32_t qf[2][4];
    ldsm4(qf[0], &Qs[(w * 16 + lar) * 20 + law]);
    ldsm4(qf[1], &Qs[(w * 16 + lar) * 20 + 8 + law]);

    const int row0 = w * 16 + g;
    float m0 = -1e30f, m1 = -1e30f, l0 = 0.f, l1 = 0.f;
    float oacc[4][4] = {};

    for (int t0 = 0; t0 < NTOK; t0 += 128) {
        __syncthreads();
        for (int idx = tid; idx < 128 * 16; idx += 256) {
            int r = idx >> 4, d = idx & 15;
            Ks[r * 20 + d] = (d < 15) ? kbu[(t0 + r) * 15 + d] : 0u;
        }
        for (int idx = tid; idx < 32 * 64; idx += 256) {
            int d = idx >> 6, j = idx & 63;
            uint32_t u = 0u;
            if (d < HDIM) {
                uint32_t lo = vb[(long)(t0 + 2 * j) * HDIM + d];
                uint32_t hi = vb[(long)(t0 + 2 * j + 1) * HDIM + d];
                u = lo | (hi << 16);
            }
            Vs[d * 68 + j] = u;
        }
        __syncthreads();

        float sacc[16][4] = {};
#pragma unroll
        for (int ks = 0; ks < 2; ks++) {
#pragma unroll
            for (int p = 0; p < 8; p++) {
                uint32_t b2[4];
                ldsm4(b2, &Ks[(p * 16 + lbr) * 20 + ks * 8 + lbw]);
                mma16(sacc[p * 2],     qf[ks], b2);
                mma16(sacc[p * 2 + 1], qf[ks], b2 + 2);
            }
        }

        float pm0 = -1e30f, pm1 = -1e30f;
#pragma unroll
        for (int nt = 0; nt < 16; nt++) {
            int c0 = t0 + nt * 8 + lc * 2;
            uint32_t u0 = bqu[((long)row0 * NTOK + c0) >> 1];
            uint32_t u1 = bqu[((long)(row0 + 8) * NTOK + c0) >> 1];
            sacc[nt][0] += b2f(u0 & 0xFFFF);
            sacc[nt][1] += b2f(u0 >> 16);
            sacc[nt][2] += b2f(u1 & 0xFFFF);
            sacc[nt][3] += b2f(u1 >> 16);
            pm0 = fmaxf(pm0, fmaxf(sacc[nt][0], sacc[nt][1]));
            pm1 = fmaxf(pm1, fmaxf(sacc[nt][2], sacc[nt][3]));
        }
        pm0 = fmaxf(pm0, __shfl_xor_sync(~0u, pm0, 1));
        pm0 = fmaxf(pm0, __shfl_xor_sync(~0u, pm0, 2));
        pm1 = fmaxf(pm1, __shfl_xor_sync(~0u, pm1, 1));
        pm1 = fmaxf(pm1, __shfl_xor_sync(~0u, pm1, 2));
        float nm0 = fmaxf(m0, pm0), nm1 = fmaxf(m1, pm1);
        float f0 = __expf(m0 - nm0), f1 = __expf(m1 - nm1);
        m0 = nm0; m1 = nm1;

        float ps0 = 0.f, ps1 = 0.f;
        uint32_t pf[8][4];
#pragma unroll
        for (int k2 = 0; k2 < 8; k2++) {
            float e00 = __expf(sacc[2 * k2][0] - m0);
            float e01 = __expf(sacc[2 * k2][1] - m0);
            float e10 = __expf(sacc[2 * k2][2] - m1);
            float e11 = __expf(sacc[2 * k2][3] - m1);
            float e20 = __expf(sacc[2 * k2 + 1][0] - m0);
            float e21 = __expf(sacc[2 * k2 + 1][1] - m0);
            float e30 = __expf(sacc[2 * k2 + 1][2] - m1);
            float e31 = __expf(sacc[2 * k2 + 1][3] - m1);
            ps0 += e00 + e01 + e20 + e21;
            ps1 += e10 + e11 + e30 + e31;
            pf[k2][0] = pk(e00, e01);
            pf[k2][1] = pk(e10, e11);
            pf[k2][2] = pk(e20, e21);
            pf[k2][3] = pk(e30, e31);
        }
        ps0 += __shfl_xor_sync(~0u, ps0, 1);
        ps0 += __shfl_xor_sync(~0u, ps0, 2);
        ps1 += __shfl_xor_sync(~0u, ps1, 1);
        ps1 += __shfl_xor_sync(~0u, ps1, 2);
        l0 = l0 * f0 + ps0;
        l1 = l1 * f1 + ps1;

#pragma unroll
        for (int nt = 0; nt < 4; nt++) {
            oacc[nt][0] *= f0; oacc[nt][1] *= f0;
            oacc[nt][2] *= f1; oacc[nt][3] *= f1;
        }
#pragma unroll
        for (int k2 = 0; k2 < 8; k2++) {
            uint32_t ba[4], bb[4];
            ldsm4(ba, &Vs[lbr * 68 + k2 * 8 + lbw]);
            ldsm4(bb, &Vs[(lbr + 16) * 68 + k2 * 8 + lbw]);
            mma16(oacc[0], pf[k2], ba);
            mma16(oacc[1], pf[k2], ba + 2);
            mma16(oacc[2], pf[k2], bb);
            mma16(oacc[3], pf[k2], bb + 2);
        }
    }

    float i0 = 1.f / l0, i1 = 1.f / l1;
    uint16_t* ob = outp + (long)(win * NTOK + qt * 128 + w * 16) * CP + hh * HDIM;
#pragma unroll
    for (int nt = 0; nt < 4; nt++) {
        int c = nt * 8 + lc * 2;
        if (c < HDIM) {
            *(uint32_t*)&ob[(long)g * CP + c] = pk(oacc[nt][0] * i0, oacc[nt][1] * i0);
            *(uint32_t*)&ob[(long)(g + 8) * CP + c] = pk(oacc[nt][2] * i1, oacc[nt][3] * i1);
        }
    }
}

// ---------------- host launch (dual-stream fork/join for graph capture) ----------------
extern "C" void kernel_launch(void* const* d_in, const int* in_sizes, int n_in,
                              void* d_out, int out_size) {
    const float* x      = (const float*)d_in[0];
    const int*   rpi    = (const int*)  d_in[4];
    const float* g1     = (const float*)d_in[7];
    const float* b1     = (const float*)d_in[8];
    const float* qkv_w  = (const float*)d_in[9];
    const float* qkv_b  = (const float*)d_in[10];
    const float* rpb    = (const float*)d_in[11];
    const float* proj_w = (const float*)d_in[12];
    const float* proj_b = (const float*)d_in[13];
    const float* cw1    = (const float*)d_in[14];
    const float* cb1    = (const float*)d_in[15];
    const float* cw2    = (const float*)d_in[16];
    const float* cb2    = (const float*)d_in[17];
    const float* caw1   = (const float*)d_in[18];
    const float* cab1   = (const float*)d_in[19];
    const float* caw2   = (const float*)d_in[20];
    const float* cab2   = (const float*)d_in[21];
    const float* g2     = (const float*)d_in[22];
    const float* b2     = (const float*)d_in[23];
    const float* fc1_w  = (const float*)d_in[24];
    const float* fc1_b  = (const float*)d_in[25];
    const float* fc2_w  = (const float*)d_in[26];
    const float* fc2_b  = (const float*)d_in[27];
    float* outp = (float*)d_out;

    uint16_t *p_xn, *p_ln2, *p_ao, *p_y1, *p_y2, *p_qkv, *p_h, *p_bt;
    uint16_t *p_w1m, *p_w2m, *p_wq, *p_wp, *p_wf1, *p_wf2;
    float *p_x1, *p_pool, *p_catt;
    cudaGetSymbolAddress((void**)&p_xn,   g_xn);
    cudaGetSymbolAddress((void**)&p_ln2,  g_ln2);
    cudaGetSymbolAddress((void**)&p_ao,   g_ao);
    cudaGetSymbolAddress((void**)&p_x1,   g_x1);
    cudaGetSymbolAddress((void**)&p_y1,   g_y1);
    cudaGetSymbolAddress((void**)&p_y2,   g_y2);
    cudaGetSymbolAddress((void**)&p_qkv,  g_qkv);
    cudaGetSymbolAddress((void**)&p_h,    g_hbuf);
    cudaGetSymbolAddress((void**)&p_bt,   g_biasT);
    cudaGetSymbolAddress((void**)&p_w1m,  g_w1m);
    cudaGetSymbolAddress((void**)&p_w2m,  g_w2m);
    cudaGetSymbolAddress((void**)&p_wq,   g_wq);
    cudaGetSymbolAddress((void**)&p_wp,   g_wp);
    cudaGetSymbolAddress((void**)&p_wf1,  g_wf1);
    cudaGetSymbolAddress((void**)&p_wf2,  g_wf2);
    cudaGetSymbolAddress((void**)&p_pool, g_pool);
    cudaGetSymbolAddress((void**)&p_catt, g_catt);

    static bool attrs_set = false;
    if (!attrs_set) {
        cudaFuncSetAttribute(mma_fc1, cudaFuncAttributeMaxDynamicSharedMemorySize, FC1_SMEM);
        attrs_set = true;
    }

    // one-time side-stream + events
    static cudaStream_t s1 = nullptr;
    static cudaEvent_t evStart = nullptr, evLN1 = nullptr, evJoin = nullptr;
    if (s1 == nullptr) {
        cudaStreamCreateWithFlags(&s1, cudaStreamNonBlocking);
        cudaEventCreateWithFlags(&evStart, cudaEventDisableTiming);
        cudaEventCreateWithFlags(&evLN1, cudaEventDisableTiming);
        cudaEventCreateWithFlags(&evJoin, cudaEventDisableTiming);
    }

    // fork
    cudaEventRecord(evStart, 0);
    cudaStreamWaitEvent(s1, evStart, 0);

    // ---- side stream s1: conv/proj/mlp weight prep, then conv branch ----
    repack1_kernel<<<(27 * 64 * 192 + 255) / 256, 256, 0, s1>>>(cw1, p_w1m);
    repack2_kernel<<<(27 * 192 * 64 + 255) / 256, 256, 0, s1>>>(cw2, p_w2m);
    wpack_kernel<<<(180 * 192 + 255) / 256, 256, 0, s1>>>(proj_w, p_wp, 180, 180, 192);
    wpack_kernel<<<(720 * 192 + 255) / 256, 256, 0, s1>>>(fc1_w, p_wf1, 720, 180, 192);
    wpack_kernel<<<(180 * HIDP + 255) / 256, 256, 0, s1>>>(fc2_w, p_wf2, 180, 720, HIDP);
    zero_pool_kernel<<<1, 384, 0, s1>>>(p_pool);

    // ---- main stream: attention-path prep + LN1 ----
    wpack_kernel<<<(540 * 192 + 255) / 256, 256>>>(qkv_w, p_wq, 540, 180, 192);
    biasprep_kernel<<<512, 512>>>(rpi, rpb, p_bt);
    ln_kernel<<<LT / 8, 256>>>(x, CC, g1, b1, p_xn, CP);
    cudaEventRecord(evLN1, 0);

    // ---- s1: conv branch (needs xn) ----
    cudaStreamWaitEvent(s1, evLN1, 0);
    mma_conv<1><<<LT / 128, 256, 0, s1>>>(p_xn, p_w1m, cb1, p_y1);
    mma_conv<2><<<dim3(LT / 128, 3), 256, 0, s1>>>(p_y1, p_w2m, cb2, p_y2);
    pooled_kernel<<<LT / 64, 192, 0, s1>>>(p_y2, p_pool);
    catt_kernel<<<1, 192, 0, s1>>>(p_pool, caw1, cab1, caw2, cab2, p_catt);
    cudaEventRecord(evJoin, s1);

    // ---- main stream: window attention path (concurrent with conv branch) ----
    mma_gemm<0, true><<<dim3(LT / 128, 9), 256>>>(p_xn, CP, p_wq, qkv_b, p_qkv,
                                                  540, 192, 0, nullptr, nullptr, nullptr);
    attn_mma<<<dim3(4, NWIN * NHEADS), 256>>>(p_qkv, p_bt, p_ao);

    // join: proj needs y2 + catt (s1) and wp (s1)
    cudaStreamWaitEvent(0, evJoin, 0);
    mma_gemm<1, false><<<dim3(LT / 128, 3), 256>>>(p_ao, CP, p_wp, proj_b, p_x1,
                                                   180, 192, 0, x, p_y2, p_catt);

    // MLP
    ln_kernel<<<LT / 8, 256>>>(p_x1, CC, g2, b2, p_ln2, CP);
    mma_fc1<<<dim3(LT / 128, 6), 256, FC1_SMEM>>>(p_ln2, p_wf1, fc1_b, (uint32_t*)p_h);
    mma_gemm<3, false><<<dim3(LT / 128, 3), 256>>>(p_h, HIDP, p_wf2, fc2_b, outp,
                                                   180, HIDP, 0, p_x1, nullptr, nullptr);
}